// round 6
// baseline (speedup 1.0000x reference)
#include <cuda_runtime.h>
#include <cuda_bf16.h>
#include <cstdint>
#include <cstddef>
#include <math.h>

#define B_   2
#define N_   2048
#define HID_ 1024
#define H_   16
#define D_   64
#define BH_  (B_*H_)     // 32
#define M_   (B_*H_*0 + B_*N_)   // 4096
#define TOPK_ 64

// fp32 scratch
__device__ float g_Qh[BH_*N_*D_];             // [bh][n][d] (pre-scaled 0.125)
__device__ float g_Kh[BH_*N_*D_];
__device__ float g_Vh[BH_*N_*D_];
__device__ float g_ctx[B_*N_*HID_];

// bf16 scratch
__device__ __nv_bfloat16 g_Qb[BH_*N_*D_];     // bf16(Qh)
__device__ __nv_bfloat16 g_Kb[BH_*N_*D_];     // bf16(Kh)
__device__ __nv_bfloat16 g_Sb[(size_t)BH_*N_*N_];  // 268 MB approx scores
__device__ __nv_bfloat16 g_Vxhi[B_*N_*HID_];
__device__ __nv_bfloat16 g_Vxlo[B_*N_*HID_];
__device__ __nv_bfloat16 g_Whi[2*HID_*HID_];  // wv, wo
__device__ __nv_bfloat16 g_Wlo[2*HID_*HID_];
__device__ __nv_bfloat16 g_Chi[B_*N_*HID_];
__device__ __nv_bfloat16 g_Clo[B_*N_*HID_];

// ---------------------------------------------------------------------------
#define LDSM_X4(r0,r1,r2,r3,addr) \
    asm volatile("ldmatrix.sync.aligned.m8n8.x4.shared.b16 {%0,%1,%2,%3}, [%4];" \
        : "=r"(r0), "=r"(r1), "=r"(r2), "=r"(r3) : "r"(addr))
#define LDSM_X2(r0,r1,addr) \
    asm volatile("ldmatrix.sync.aligned.m8n8.x2.shared.b16 {%0,%1}, [%2];" \
        : "=r"(r0), "=r"(r1) : "r"(addr))
#define MMA16816(c0,c1,c2,c3,a0,a1,a2,a3,b0,b1) \
    asm volatile("mma.sync.aligned.m16n8k16.row.col.f32.bf16.bf16.f32 " \
        "{%0,%1,%2,%3}, {%4,%5,%6,%7}, {%8,%9}, {%0,%1,%2,%3};" \
        : "+f"(c0), "+f"(c1), "+f"(c2), "+f"(c3) \
        : "r"(a0), "r"(a1), "r"(a2), "r"(a3), "r"(b0), "r"(b1))

__device__ __forceinline__ uint32_t smem_u32(const void* p) {
    uint32_t a;
    asm("{ .reg .u64 t; cvta.to.shared.u64 t, %1; cvt.u32.u64 %0, t; }"
        : "=r"(a) : "l"(p));
    return a;
}

// ---------------------------------------------------------------------------
// Split fp32 -> bf16 hi + lo
// ---------------------------------------------------------------------------
__global__ __launch_bounds__(256) void split_kernel(
    const float* __restrict__ src, __nv_bfloat16* __restrict__ hi,
    __nv_bfloat16* __restrict__ lo, int n4)
{
    int i = blockIdx.x * 256 + threadIdx.x;
    if (i >= n4) return;
    float4 x = ((const float4*)src)[i];
    __nv_bfloat16 h0 = __float2bfloat16_rn(x.x);
    __nv_bfloat16 h1 = __float2bfloat16_rn(x.y);
    __nv_bfloat16 h2 = __float2bfloat16_rn(x.z);
    __nv_bfloat16 h3 = __float2bfloat16_rn(x.w);
    __nv_bfloat16 l0 = __float2bfloat16_rn(x.x - __bfloat162float(h0));
    __nv_bfloat16 l1 = __float2bfloat16_rn(x.y - __bfloat162float(h1));
    __nv_bfloat16 l2 = __float2bfloat16_rn(x.z - __bfloat162float(h2));
    __nv_bfloat16 l3 = __float2bfloat16_rn(x.w - __bfloat162float(h3));
    __nv_bfloat162 a, b, c, d;
    a.x = h0; a.y = h1; b.x = h2; b.y = h3;
    c.x = l0; c.y = l1; d.x = l2; d.y = l3;
    ((__nv_bfloat162*)hi)[2*i]   = a;
    ((__nv_bfloat162*)hi)[2*i+1] = b;
    ((__nv_bfloat162*)lo)[2*i]   = c;
    ((__nv_bfloat162*)lo)[2*i+1] = d;
}

// fp32 -> bf16 (single)
__global__ __launch_bounds__(256) void cvt_bf16_kernel(
    const float* __restrict__ src, __nv_bfloat16* __restrict__ dst, int n4)
{
    int i = blockIdx.x * 256 + threadIdx.x;
    if (i >= n4) return;
    float4 x = ((const float4*)src)[i];
    __nv_bfloat162 a, b;
    a.x = __float2bfloat16_rn(x.x); a.y = __float2bfloat16_rn(x.y);
    b.x = __float2bfloat16_rn(x.z); b.y = __float2bfloat16_rn(x.w);
    ((__nv_bfloat162*)dst)[2*i]   = a;
    ((__nv_bfloat162*)dst)[2*i+1] = b;
}

// ---------------------------------------------------------------------------
// HMMA split-bf16 GEMM (verbatim R5): Out[n,o] = sum_i X[n,i]*W[o,i] + bias[o]
// ---------------------------------------------------------------------------
#define TS_   5120          // tile size in bf16 (128 rows * 40)

__global__ __launch_bounds__(256, 2) void hmma_gemm(
    const __nv_bfloat16* __restrict__ Ahi, const __nv_bfloat16* __restrict__ Alo,
    const __nv_bfloat16* __restrict__ Bhi, const __nv_bfloat16* __restrict__ Blo,
    const float* __restrict__ bias, float* __restrict__ Out, int mode)
{
    __shared__ __align__(16) __nv_bfloat16 smbuf[4 * TS_];   // 40960 B
    int tid  = threadIdx.x;
    int wid  = tid >> 5, lane = tid & 31;
    int wm   = wid >> 2;
    int wn   = wid & 3;
    int o0   = blockIdx.x * 128;
    int n0   = blockIdx.y * 128;

    uint32_t smb = smem_u32(smbuf);

    float c[4][4][4];
#pragma unroll
    for (int mt = 0; mt < 4; mt++)
#pragma unroll
        for (int nt = 0; nt < 4; nt++)
#pragma unroll
            for (int r = 0; r < 4; r++) c[mt][nt][r] = 0.f;

    int rowm[8], segm[8];
    const __nv_bfloat16* gbase[8];
#pragma unroll
    for (int t = 0; t < 8; t++) {
        int tile = t >> 1;
        int sub  = ((t & 1) << 8) + tid;
        rowm[t] = sub >> 2; segm[t] = sub & 3;
        const __nv_bfloat16* base =
            (tile == 0) ? Ahi : (tile == 1) ? Alo : (tile == 2) ? Bhi : Blo;
        int grow = (tile < 2) ? (n0 + rowm[t]) : (o0 + rowm[t]);
        gbase[t] = base + (size_t)grow * HID_ + segm[t] * 8;
    }
    uint32_t soff[8];
#pragma unroll
    for (int t = 0; t < 8; t++)
        soff[t] = (uint32_t)(((t >> 1) * TS_ + rowm[t] * 40 + segm[t] * 8) * 2);

    uint32_t laneA = (uint32_t)((lane & 15) * 80 + (lane >> 4) * 16);
    uint32_t laneB = (uint32_t)((lane & 7) * 80 + ((lane >> 3) & 1) * 16);
    uint32_t aBase0 = smb + (uint32_t)(wm * 64 * 80) + laneA;
    uint32_t bBase0 = smb + (uint32_t)(wn * 32 * 80) + laneB;

    uint4 pf[8];
#pragma unroll
    for (int t = 0; t < 8; t++) pf[t] = *(const uint4*)gbase[t];
#pragma unroll
    for (int t = 0; t < 8; t++) *(uint4*)((char*)smbuf + soff[t]) = pf[t];
    __syncthreads();

    for (int kc = 0; kc < 32; kc++) {
        if (kc < 31) {
#pragma unroll
            for (int t = 0; t < 8; t++)
                pf[t] = *(const uint4*)(gbase[t] + (kc + 1) * 32);
        }

#pragma unroll
        for (int pass = 0; pass < 3; pass++) {
            uint32_t aT = aBase0 + (uint32_t)(((pass == 2) ? TS_ : 0) * 2);
            uint32_t bT = bBase0 + (uint32_t)((((pass == 1) ? 3 : 2) * TS_) * 2);
#pragma unroll
            for (int k16 = 0; k16 < 2; k16++) {
                uint32_t a[4][4];
#pragma unroll
                for (int mt = 0; mt < 4; mt++)
                    LDSM_X4(a[mt][0], a[mt][1], a[mt][2], a[mt][3],
                            aT + (uint32_t)(mt * 1280 + k16 * 32));
                uint32_t bf[4][2];
#pragma unroll
                for (int nt = 0; nt < 4; nt++)
                    LDSM_X2(bf[nt][0], bf[nt][1],
                            bT + (uint32_t)(nt * 640 + k16 * 32));
#pragma unroll
                for (int mt = 0; mt < 4; mt++)
#pragma unroll
                    for (int nt = 0; nt < 4; nt++)
                        MMA16816(c[mt][nt][0], c[mt][nt][1], c[mt][nt][2], c[mt][nt][3],
                                 a[mt][0], a[mt][1], a[mt][2], a[mt][3],
                                 bf[nt][0], bf[nt][1]);
            }
        }

        if (kc < 31) {
            __syncthreads();
#pragma unroll
            for (int t = 0; t < 8; t++)
                *(uint4*)((char*)smbuf + soff[t]) = pf[t];
            __syncthreads();
        }
    }

    int row_l = lane >> 2;
    int col_l = (lane & 3) * 2;
#pragma unroll
    for (int nt = 0; nt < 4; nt++) {
        int o = o0 + wn * 32 + nt * 8 + col_l;
        float bv0 = __ldg(bias + o);
        float bv1 = __ldg(bias + o + 1);
#pragma unroll
        for (int mt = 0; mt < 4; mt++) {
            int n = n0 + wm * 64 + mt * 16 + row_l;
#pragma unroll
            for (int half = 0; half < 2; half++) {
                int nn2 = n + half * 8;
                size_t idx;
                if (mode == 0) {
                    int b = nn2 >> 11, nr = nn2 & 2047;
                    int h = o >> 6,  d0 = o & 63;
                    idx = (((size_t)(b * H_ + h) * N_) + nr) * D_ + d0;
                } else {
                    idx = (size_t)nn2 * HID_ + o;
                }
                float2 vv;
                vv.x = c[mt][nt][half * 2 + 0] + bv0;
                vv.y = c[mt][nt][half * 2 + 1] + bv1;
                *(float2*)(Out + idx) = vv;
            }
        }
    }
}

// ---------------------------------------------------------------------------
// Approx scores: bf16 HMMA, Sb[bh][q][k] = bf16( dot64(Qb[q], Kb[k]) )
// 128x128 tile, K=64 loaded once into 4 tile slots (Q d0/d1, K d0/d1).
// ---------------------------------------------------------------------------
__global__ __launch_bounds__(256, 2) void scores_approx(void)
{
    __shared__ __align__(16) __nv_bfloat16 smbuf[4 * TS_];   // 40960 B
    int tid  = threadIdx.x;
    int wid  = tid >> 5, lane = tid & 31;
    int wm   = wid >> 2;
    int wn   = wid & 3;
    int bh   = blockIdx.z;
    int k0   = blockIdx.x * 128;
    int q0   = blockIdx.y * 128;

    const __nv_bfloat16* Qb = g_Qb + (size_t)bh * N_ * D_;
    const __nv_bfloat16* Kb = g_Kb + (size_t)bh * N_ * D_;
    uint32_t smb = smem_u32(smbuf);

    float c[4][4][4];
#pragma unroll
    for (int mt = 0; mt < 4; mt++)
#pragma unroll
        for (int nt = 0; nt < 4; nt++)
#pragma unroll
            for (int r = 0; r < 4; r++) c[mt][nt][r] = 0.f;

    // load 4 tile slots: 0/1 = Q dims 0-31 / 32-63; 2/3 = K dims 0-31 / 32-63
#pragma unroll
    for (int t = 0; t < 8; t++) {
        int tile = t >> 1;
        int sub  = ((t & 1) << 8) + tid;
        int row  = sub >> 2, seg = sub & 3;
        const __nv_bfloat16* src =
            ((tile < 2) ? (Qb + (size_t)(q0 + row) * D_)
                        : (Kb + (size_t)(k0 + row) * D_))
            + (tile & 1) * 32 + seg * 8;
        *(uint4*)((char*)smbuf + (tile * TS_ + row * 40 + seg * 8) * 2) =
            *(const uint4*)src;
    }
    __syncthreads();

    uint32_t laneA = (uint32_t)((lane & 15) * 80 + (lane >> 4) * 16);
    uint32_t laneB = (uint32_t)((lane & 7) * 80 + ((lane >> 3) & 1) * 16);
    uint32_t aBase0 = smb + (uint32_t)(wm * 64 * 80) + laneA;
    uint32_t bBase0 = smb + (uint32_t)(wn * 32 * 80) + laneB;

#pragma unroll
    for (int chunk = 0; chunk < 2; chunk++) {
        uint32_t aT = aBase0 + (uint32_t)((chunk ? TS_ : 0) * 2);
        uint32_t bT = bBase0 + (uint32_t)(((chunk ? 3 : 2) * TS_) * 2);
#pragma unroll
        for (int k16 = 0; k16 < 2; k16++) {
            uint32_t a[4][4];
#pragma unroll
            for (int mt = 0; mt < 4; mt++)
                LDSM_X4(a[mt][0], a[mt][1], a[mt][2], a[mt][3],
                        aT + (uint32_t)(mt * 1280 + k16 * 32));
            uint32_t bf[4][2];
#pragma unroll
            for (int nt = 0; nt < 4; nt++)
                LDSM_X2(bf[nt][0], bf[nt][1],
                        bT + (uint32_t)(nt * 640 + k16 * 32));
#pragma unroll
            for (int mt = 0; mt < 4; mt++)
#pragma unroll
                for (int nt = 0; nt < 4; nt++)
                    MMA16816(c[mt][nt][0], c[mt][nt][1], c[mt][nt][2], c[mt][nt][3],
                             a[mt][0], a[mt][1], a[mt][2], a[mt][3],
                             bf[nt][0], bf[nt][1]);
        }
    }

    int row_l = lane >> 2;
    int col_l = (lane & 3) * 2;
    __nv_bfloat16* Sb = g_Sb + (size_t)bh * N_ * N_;
#pragma unroll
    for (int nt = 0; nt < 4; nt++) {
        int o = k0 + wn * 32 + nt * 8 + col_l;
#pragma unroll
        for (int mt = 0; mt < 4; mt++) {
            int n = q0 + wm * 64 + mt * 16 + row_l;
#pragma unroll
            for (int half = 0; half < 2; half++) {
                int q = n + half * 8;
                __nv_bfloat162 p;
                p.x = __float2bfloat16_rn(c[mt][nt][half * 2 + 0]);
                p.y = __float2bfloat16_rn(c[mt][nt][half * 2 + 1]);
                *(__nv_bfloat162*)(Sb + (size_t)q * N_ + o) = p;
            }
        }
    }
}

// ---------------------------------------------------------------------------
// select_pv: per warp (1 query):
//  approx top-128 candidates from bf16 scores, exact fp32 rescoring of the
//  128 (bit-identical fmaf chain), exact top-64 + ties-by-lowest-index,
//  softmax, PV.
// ---------------------------------------------------------------------------
__device__ __forceinline__ unsigned fflip(float f) {
    unsigned u = __float_as_uint(f);
    return (u & 0x80000000u) ? ~u : (u | 0x80000000u);
}
__device__ __forceinline__ float funflip(unsigned u) {
    unsigned v = (u & 0x80000000u) ? (u & 0x7FFFFFFFu) : ~u;
    return __uint_as_float(v);
}

__global__ __launch_bounds__(256) void select_pv(void)
{
    __shared__ unsigned short cidx[8][128];
    __shared__ unsigned short eqk[8][128];
    __shared__ float qrow[8][64];
    __shared__ int   sk[8][64];
    __shared__ float sv[8][64];
    __shared__ float pw[8][64];
    __shared__ int   ek[8][64];

    int w    = threadIdx.x >> 5;
    int lane = threadIdx.x & 31;
    int gq   = blockIdx.x * 8 + w;
    int bh   = gq >> 11;
    int qr   = gq & 2047;
    unsigned ltmask = (1u << lane) - 1u;

    // q row (pre-scaled by 0.125) into smem
    const float* Qp = g_Qh + ((size_t)bh * N_ + qr) * D_;
    if (lane < 16) *(float4*)&qrow[w][lane * 4] = ((const float4*)Qp)[lane];
    __syncwarp();

    // load 2048 bf16 approx scores, flip halves for unsigned ordering
    const uint4* Sp = (const uint4*)(g_Sb + ((size_t)bh * N_ + qr) * N_);
    uint32_t pk[32];
#pragma unroll
    for (int it = 0; it < 8; it++) {
        uint4 q4 = Sp[it * 32 + lane];
        uint32_t vs[4] = {q4.x, q4.y, q4.z, q4.w};
#pragma unroll
        for (int r = 0; r < 4; r++) {
            uint32_t v = vs[r];
            uint32_t lo = v & 0xFFFFu, hi = v >> 16;
            lo = (lo & 0x8000u) ? (~lo & 0xFFFFu) : (lo | 0x8000u);
            hi = (hi & 0x8000u) ? (~hi & 0xFFFFu) : (hi | 0x8000u);
            pk[it * 4 + r] = (hi << 16) | lo;
        }
    }

    // 16-bit bitwise select: X16 = 128th-largest flipped-bf16 value
    uint32_t t16 = 0;
#pragma unroll
    for (int bit = 15; bit >= 0; bit--) {
        uint32_t tt  = t16 | (1u << bit);
        uint32_t tt2 = (tt << 16) | tt;
        uint32_t s2  = 0;
#pragma unroll
        for (int r = 0; r < 32; r++)
            s2 += __vcmpgeu2(pk[r], tt2) & 0x00010001u;
        int cnum = (int)((s2 >> 16) + (s2 & 0xFFFFu));
        cnum = __reduce_add_sync(0xffffffffu, cnum);
        if (cnum >= 128) t16 = tt;
    }

    // compact: all strictly-greater, then fill to 128 with == X16 (any
    // deterministic order -- these fills are provably outside the true top-64)
    int g1 = 0, g2 = 0;
#pragma unroll
    for (int r = 0; r < 32; r++) {
#pragma unroll
        for (int h = 0; h < 2; h++) {
            uint32_t v = h ? (pk[r] >> 16) : (pk[r] & 0xFFFFu);
            int kix = ((r >> 2) * 32 + lane) * 8 + (r & 3) * 2 + h;
            bool gt = (v > t16), eq = (v == t16);
            unsigned mg = __ballot_sync(0xffffffffu, gt);
            unsigned me = __ballot_sync(0xffffffffu, eq);
            if (gt) cidx[w][g1 + __popc(mg & ltmask)] = (unsigned short)kix;
            if (eq) {
                int p = g2 + __popc(me & ltmask);
                if (p < 128) eqk[w][p] = (unsigned short)kix;
            }
            g1 += __popc(mg);
            g2 += __popc(me);
        }
    }
    __syncwarp();
    for (int i = lane; i < 128 - g1; i += 32) cidx[w][g1 + i] = eqk[w][i];
    __syncwarp();

    // exact fp32 rescoring of 128 candidates: 4 per lane, sequential fmaf
    // chain over d = 0..63 (bit-identical to the old scores_kernel values)
    int   kj[4];
    float acc[4];
#pragma unroll
    for (int j = 0; j < 4; j++) {
        kj[j]  = cidx[w][lane + 32 * j];
        acc[j] = 0.f;
    }
    const float* Kb = g_Kh + (size_t)bh * N_ * D_;
#pragma unroll
    for (int d4 = 0; d4 < 16; d4++) {
        float4 kv[4];
#pragma unroll
        for (int j = 0; j < 4; j++)
            kv[j] = *(const float4*)(Kb + (size_t)kj[j] * D_ + d4 * 4);
        float q0v = qrow[w][d4 * 4 + 0];
        float q1v = qrow[w][d4 * 4 + 1];
        float q2v = qrow[w][d4 * 4 + 2];
        float q3v = qrow[w][d4 * 4 + 3];
#pragma unroll
        for (int j = 0; j < 4; j++) {
            acc[j] = fmaf(q0v, kv[j].x, acc[j]);
            acc[j] = fmaf(q1v, kv[j].y, acc[j]);
            acc[j] = fmaf(q2v, kv[j].z, acc[j]);
            acc[j] = fmaf(q3v, kv[j].w, acc[j]);
        }
    }

    // exact 64th-largest among the 128
    unsigned fu[4];
#pragma unroll
    for (int j = 0; j < 4; j++) fu[j] = fflip(acc[j]);
    unsigned X = 0;
#pragma unroll
    for (int bit = 31; bit >= 0; bit--) {
        unsigned tt = X | (1u << bit);
        int cnum = (fu[0] >= tt) + (fu[1] >= tt) + (fu[2] >= tt) + (fu[3] >= tt);
        cnum = __reduce_add_sync(0xffffffffu, cnum);
        if (cnum >= TOPK_) X = tt;
    }

    // collect: strictly-greater, then ties (== X) by lowest key index
    int h1 = 0, h2 = 0;
#pragma unroll
    for (int j = 0; j < 4; j++) {
        bool gt = (fu[j] > X), eq = (fu[j] == X);
        unsigned mg = __ballot_sync(0xffffffffu, gt);
        unsigned me = __ballot_sync(0xffffffffu, eq);
        if (gt) {
            int p = h1 + __popc(mg & ltmask);
            sk[w][p] = kj[j];
            sv[w][p] = acc[j];
        }
        if (eq) {
            int p = h2 + __popc(me & ltmask);
            if (p < 64) ek[w][p] = kj[j];
        }
        h1 += __popc(mg);
        h2 += __popc(me);
    }
    __syncwarp();
    if (lane == 0) {
        int need = TOPK_ - h1;
        int ec   = h2 > 64 ? 64 : h2;
        float xv = funflip(X);
        for (int s2 = 0; s2 < need; s2++) {
            int best = 0x7FFFFFFF, bi = 0;
            for (int e = 0; e < ec; e++) {
                int v2 = ek[w][e];
                if (v2 < best) { best = v2; bi = e; }
            }
            ek[w][bi] = 0x7FFFFFFF;
            sk[w][h1 + s2] = best;
            sv[w][h1 + s2] = xv;
        }
    }
    __syncwarp();

    // softmax over selected 64
    float v0 = sv[w][lane];
    float v1 = sv[w][lane + 32];
    float mx = funflip(__reduce_max_sync(0xffffffffu,
                 (unsigned)max(fflip(v0), fflip(v1))));
    float p0 = expf(v0 - mx);
    float p1 = expf(v1 - mx);
    pw[w][lane]      = p0;
    pw[w][lane + 32] = p1;
    float z = p0 + p1;
#pragma unroll
    for (int off = 16; off > 0; off >>= 1)
        z += __shfl_xor_sync(0xffffffffu, z, off);
    float invZ = 1.0f / z;

    // PV
    const float* Vb = g_Vh + (size_t)bh * N_ * D_;
    float acc0 = 0.f, acc1 = 0.f;
#pragma unroll 4
    for (int j = 0; j < 64; j++) {
        float p  = pw[w][j];
        int   kv2 = sk[w][j];
        acc0 += p * Vb[(size_t)kv2 * D_ + lane];
        acc1 += p * Vb[(size_t)kv2 * D_ + lane + 32];
    }

    int b = bh >> 4, h = bh & 15;
    size_t obase = ((size_t)(b * N_ + qr)) * HID_ + h * D_ + lane;
    g_ctx[obase]      = acc0 * invZ;
    g_ctx[obase + 32] = acc1 * invZ;
}

// ---------------------------------------------------------------------------
// SGEMM fp32 (verbatim R3) -- Q and K projections ONLY (numerics frozen)
// ---------------------------------------------------------------------------
__global__ __launch_bounds__(256, 2) void sgemm_nt(
    const float* __restrict__ X, const float* __restrict__ W,
    const float* __restrict__ bias, float* __restrict__ Out,
    int mode, float oscale)
{
    const int K = HID_;
    __shared__ float As[2][8][128];
    __shared__ float Bs[2][8][128];
    int tid = threadIdx.x;
    int n0 = blockIdx.y * 128;
    int o0 = blockIdx.x * 128;

    int lrow = tid >> 1;
    int lkq  = (tid & 1) * 4;
    const float* Xp = X + (size_t)(n0 + lrow) * K + lkq;
    const float* Wp = W + (size_t)(o0 + lrow) * K + lkq;

    {
        float4 xa = *(const float4*)Xp;
        float4 wa = *(const float4*)Wp;
        As[0][lkq+0][lrow] = xa.x; As[0][lkq+1][lrow] = xa.y;
        As[0][lkq+2][lrow] = xa.z; As[0][lkq+3][lrow] = xa.w;
        Bs[0][lkq+0][lrow] = wa.x; Bs[0][lkq+1][lrow] = wa.y;
        Bs[0][lkq+2][lrow] = wa.z; Bs[0][lkq+3][lrow] = wa.w;
    }
    __syncthreads();

    int tx = tid & 15, ty = tid >> 4;
    float c[8][8];
#pragma unroll
    for (int i = 0; i < 8; i++)
#pragma unroll
        for (int j = 0; j < 8; j++) c[i][j] = 0.f;

    const int NSTEP = K / 8;
#pragma unroll 2
    for (int k0 = 0; k0 < NSTEP; k0++) {
        int cur = k0 & 1;
        float4 xn, wn;
        if (k0 < NSTEP - 1) {
            xn = *(const float4*)(Xp + (k0 + 1) * 8);
            wn = *(const float4*)(Wp + (k0 + 1) * 8);
        }
#pragma unroll
        for (int kk = 0; kk < 8; kk++) {
            float a[8], b[8];
            *(float4*)&a[0] = *(const float4*)&As[cur][kk][ty*8];
            *(float4*)&a[4] = *(const float4*)&As[cur][kk][ty*8+4];
            *(float4*)&b[0] = *(const float4*)&Bs[cur][kk][tx*8];
            *(float4*)&b[4] = *(const float4*)&Bs[cur][kk][tx*8+4];
#pragma unroll
            for (int i = 0; i < 8; i++)
#pragma unroll
                for (int j = 0; j < 8; j++)
                    c[i][j] += a[i] * b[j];
        }
        if (k0 < NSTEP - 1) {
            int nxt = cur ^ 1;
            As[nxt][lkq+0][lrow] = xn.x; As[nxt][lkq+1][lrow] = xn.y;
            As[nxt][lkq+2][lrow] = xn.z; As[nxt][lkq+3][lrow] = xn.w;
            Bs[nxt][lkq+0][lrow] = wn.x; Bs[nxt][lkq+1][lrow] = wn.y;
            Bs[nxt][lkq+2][lrow] = wn.z; Bs[nxt][lkq+3][lrow] = wn.w;
            __syncthreads();
        }
    }

    float bfr[8];
#pragma unroll
    for (int j = 0; j < 8; j++) bfr[j] = __ldg(bias + o0 + tx*8 + j);

#pragma unroll
    for (int i = 0; i < 8; i++) {
        int n = n0 + ty * 8 + i;
        int o = o0 + tx * 8;
        size_t idx;
        if (mode == 0) {
            int b = n >> 11, nn = n & 2047;
            int h = o >> 6,  d  = o & 63;
            idx = (((size_t)(b * H_ + h) * N_) + nn) * D_ + d;
        } else {
            idx = (size_t)n * HID_ + o;
        }
        float4 v0, v1;
        v0.x = (c[i][0] + bfr[0]) * oscale;
        v0.y = (c[i][1] + bfr[1]) * oscale;
        v0.z = (c[i][2] + bfr[2]) * oscale;
        v0.w = (c[i][3] + bfr[3]) * oscale;
        v1.x = (c[i][4] + bfr[4]) * oscale;
        v1.y = (c[i][5] + bfr[5]) * oscale;
        v1.z = (c[i][6] + bfr[6]) * oscale;
        v1.w = (c[i][7] + bfr[7]) * oscale;
        *(float4*)(Out + idx)     = v0;
        *(float4*)(Out + idx + 4) = v1;
    }
}

// ---------------------------------------------------------------------------
extern "C" void kernel_launch(void* const* d_in, const int* in_sizes, int n_in,
                              void* d_out, int out_size)
{
    const float* q    = (const float*)d_in[0];
    const float* k    = (const float*)d_in[1];
    const float* v    = (const float*)d_in[2];
    const float* wq_w = (const float*)d_in[5];
    const float* wq_b = (const float*)d_in[6];
    const float* wk_w = (const float*)d_in[7];
    const float* wk_b = (const float*)d_in[8];
    const float* wv_w = (const float*)d_in[9];
    const float* wv_b = (const float*)d_in[10];
    const float* wo_w = (const float*)d_in[11];
    const float* wo_b = (const float*)d_in[12];
    float* out = (float*)d_out;

    float *Qh, *Kh, *Vh, *ctx;
    __nv_bfloat16 *Qb, *Kb, *Vxhi, *Vxlo, *Whi, *Wlo, *Chi, *Clo;
    cudaGetSymbolAddress((void**)&Qh,   g_Qh);
    cudaGetSymbolAddress((void**)&Kh,   g_Kh);
    cudaGetSymbolAddress((void**)&Vh,   g_Vh);
    cudaGetSymbolAddress((void**)&ctx,  g_ctx);
    cudaGetSymbolAddress((void**)&Qb,   g_Qb);
    cudaGetSymbolAddress((void**)&Kb,   g_Kb);
    cudaGetSymbolAddress((void**)&Vxhi, g_Vxhi);
    cudaGetSymbolAddress((void**)&Vxlo, g_Vxlo);
    cudaGetSymbolAddress((void**)&Whi,  g_Whi);
    cudaGetSymbolAddress((void**)&Wlo,  g_Wlo);
    cudaGetSymbolAddress((void**)&Chi,  g_Chi);
    cudaGetSymbolAddress((void**)&Clo,  g_Clo);

    const int NX4 = B_ * N_ * HID_ / 4;
    const int NW4 = HID_ * HID_ / 4;
    const int NH4 = BH_ * N_ * D_ / 4;

    split_kernel<<<NX4/256, 256>>>(v,    Vxhi, Vxlo, NX4);
    split_kernel<<<NW4/256, 256>>>(wv_w, Whi,             Wlo,             NW4);
    split_kernel<<<NW4/256, 256>>>(wo_w, Whi + HID_*HID_, Wlo + HID_*HID_, NW4);

    dim3 gProj(HID_ / 128, (B_ * N_) / 128);    // 8 x 32
    sgemm_nt<<<gProj, 256>>>(q, wq_w, wq_b, Qh, 0, 0.125f);   // frozen fp32
    sgemm_nt<<<gProj, 256>>>(k, wk_w, wk_b, Kh, 0, 1.0f);     // frozen fp32
    hmma_gemm<<<gProj, 256>>>(Vxhi, Vxlo, Whi, Wlo, wv_b, Vh, 0);

    cvt_bf16_kernel<<<NH4/256, 256>>>(Qh, Qb, NH4);
    cvt_bf16_kernel<<<NH4/256, 256>>>(Kh, Kb, NH4);

    dim3 gSc(N_ / 128, N_ / 128, BH_);          // 16 x 16 x 32
    scores_approx<<<gSc, 256>>>();

    select_pv<<<(B_ * N_ * H_) / 8, 256>>>();   // 8192 blocks, 1 warp/query

    split_kernel<<<NX4/256, 256>>>(ctx, Chi, Clo, NX4);
    hmma_gemm<<<gProj, 256>>>(Chi, Clo, Whi + HID_*HID_, Wlo + HID_*HID_,
                              wo_b, out, 1);
}

// round 7
// speedup vs baseline: 1.2903x; 1.2903x over previous
#include <cuda_runtime.h>
#include <cuda_bf16.h>
#include <cstdint>
#include <cstddef>
#include <math.h>

#define B_   2
#define N_   2048
#define HID_ 1024
#define H_   16
#define D_   64
#define BH_  (B_*H_)     // 32
#define M_   (B_*N_)     // 4096
#define TOPK_ 64

// fp32 scratch
__device__ float g_Qh[BH_*N_*D_];             // [bh][n][d] (pre-scaled 0.125)
__device__ float g_Kh[BH_*N_*D_];
__device__ float g_Vh[BH_*N_*D_];
__device__ float g_S[134217728];              // 537 MB [bh][q][k]
__device__ float g_ctx[B_*N_*HID_];

// bf16 split scratch (V path + O path only)
__device__ __nv_bfloat16 g_Vxhi[B_*N_*HID_];
__device__ __nv_bfloat16 g_Vxlo[B_*N_*HID_];
__device__ __nv_bfloat16 g_Whi[2*HID_*HID_];  // wv, wo
__device__ __nv_bfloat16 g_Wlo[2*HID_*HID_];
__device__ __nv_bfloat16 g_Chi[B_*N_*HID_];
__device__ __nv_bfloat16 g_Clo[B_*N_*HID_];

// ---------------------------------------------------------------------------
#define LDSM_X4(r0,r1,r2,r3,addr) \
    asm volatile("ldmatrix.sync.aligned.m8n8.x4.shared.b16 {%0,%1,%2,%3}, [%4];" \
        : "=r"(r0), "=r"(r1), "=r"(r2), "=r"(r3) : "r"(addr))
#define LDSM_X2(r0,r1,addr) \
    asm volatile("ldmatrix.sync.aligned.m8n8.x2.shared.b16 {%0,%1}, [%2];" \
        : "=r"(r0), "=r"(r1) : "r"(addr))
#define MMA16816(c0,c1,c2,c3,a0,a1,a2,a3,b0,b1) \
    asm volatile("mma.sync.aligned.m16n8k16.row.col.f32.bf16.bf16.f32 " \
        "{%0,%1,%2,%3}, {%4,%5,%6,%7}, {%8,%9}, {%0,%1,%2,%3};" \
        : "+f"(c0), "+f"(c1), "+f"(c2), "+f"(c3) \
        : "r"(a0), "r"(a1), "r"(a2), "r"(a3), "r"(b0), "r"(b1))

__device__ __forceinline__ uint32_t smem_u32(const void* p) {
    uint32_t a;
    asm("{ .reg .u64 t; cvta.to.shared.u64 t, %1; cvt.u32.u64 %0, t; }"
        : "=r"(a) : "l"(p));
    return a;
}

// ---------------------------------------------------------------------------
// Split fp32 -> bf16 hi + lo
// ---------------------------------------------------------------------------
__global__ __launch_bounds__(256) void split_kernel(
    const float* __restrict__ src, __nv_bfloat16* __restrict__ hi,
    __nv_bfloat16* __restrict__ lo, int n4)
{
    int i = blockIdx.x * 256 + threadIdx.x;
    if (i >= n4) return;
    float4 x = ((const float4*)src)[i];
    __nv_bfloat16 h0 = __float2bfloat16_rn(x.x);
    __nv_bfloat16 h1 = __float2bfloat16_rn(x.y);
    __nv_bfloat16 h2 = __float2bfloat16_rn(x.z);
    __nv_bfloat16 h3 = __float2bfloat16_rn(x.w);
    __nv_bfloat16 l0 = __float2bfloat16_rn(x.x - __bfloat162float(h0));
    __nv_bfloat16 l1 = __float2bfloat16_rn(x.y - __bfloat162float(h1));
    __nv_bfloat16 l2 = __float2bfloat16_rn(x.z - __bfloat162float(h2));
    __nv_bfloat16 l3 = __float2bfloat16_rn(x.w - __bfloat162float(h3));
    __nv_bfloat162 a, b, c, d;
    a.x = h0; a.y = h1; b.x = h2; b.y = h3;
    c.x = l0; c.y = l1; d.x = l2; d.y = l3;
    ((__nv_bfloat162*)hi)[2*i]   = a;
    ((__nv_bfloat162*)hi)[2*i+1] = b;
    ((__nv_bfloat162*)lo)[2*i]   = c;
    ((__nv_bfloat162*)lo)[2*i+1] = d;
}

// ---------------------------------------------------------------------------
// HMMA split-bf16 GEMM (verbatim R5)
// ---------------------------------------------------------------------------
#define TS_   5120          // tile size in bf16 (128 rows * 40)

__global__ __launch_bounds__(256, 2) void hmma_gemm(
    const __nv_bfloat16* __restrict__ Ahi, const __nv_bfloat16* __restrict__ Alo,
    const __nv_bfloat16* __restrict__ Bhi, const __nv_bfloat16* __restrict__ Blo,
    const float* __restrict__ bias, float* __restrict__ Out, int mode)
{
    __shared__ __align__(16) __nv_bfloat16 smbuf[4 * TS_];   // 40960 B
    int tid  = threadIdx.x;
    int wid  = tid >> 5, lane = tid & 31;
    int wm   = wid >> 2;
    int wn   = wid & 3;
    int o0   = blockIdx.x * 128;
    int n0   = blockIdx.y * 128;

    uint32_t smb = smem_u32(smbuf);

    float c[4][4][4];
#pragma unroll
    for (int mt = 0; mt < 4; mt++)
#pragma unroll
        for (int nt = 0; nt < 4; nt++)
#pragma unroll
            for (int r = 0; r < 4; r++) c[mt][nt][r] = 0.f;

    int rowm[8], segm[8];
    const __nv_bfloat16* gbase[8];
#pragma unroll
    for (int t = 0; t < 8; t++) {
        int tile = t >> 1;
        int sub  = ((t & 1) << 8) + tid;
        rowm[t] = sub >> 2; segm[t] = sub & 3;
        const __nv_bfloat16* base =
            (tile == 0) ? Ahi : (tile == 1) ? Alo : (tile == 2) ? Bhi : Blo;
        int grow = (tile < 2) ? (n0 + rowm[t]) : (o0 + rowm[t]);
        gbase[t] = base + (size_t)grow * HID_ + segm[t] * 8;
    }
    uint32_t soff[8];
#pragma unroll
    for (int t = 0; t < 8; t++)
        soff[t] = (uint32_t)(((t >> 1) * TS_ + rowm[t] * 40 + segm[t] * 8) * 2);

    uint32_t laneA = (uint32_t)((lane & 15) * 80 + (lane >> 4) * 16);
    uint32_t laneB = (uint32_t)((lane & 7) * 80 + ((lane >> 3) & 1) * 16);
    uint32_t aBase0 = smb + (uint32_t)(wm * 64 * 80) + laneA;
    uint32_t bBase0 = smb + (uint32_t)(wn * 32 * 80) + laneB;

    uint4 pf[8];
#pragma unroll
    for (int t = 0; t < 8; t++) pf[t] = *(const uint4*)gbase[t];
#pragma unroll
    for (int t = 0; t < 8; t++) *(uint4*)((char*)smbuf + soff[t]) = pf[t];
    __syncthreads();

    for (int kc = 0; kc < 32; kc++) {
        if (kc < 31) {
#pragma unroll
            for (int t = 0; t < 8; t++)
                pf[t] = *(const uint4*)(gbase[t] + (kc + 1) * 32);
        }

#pragma unroll
        for (int pass = 0; pass < 3; pass++) {
            uint32_t aT = aBase0 + (uint32_t)(((pass == 2) ? TS_ : 0) * 2);
            uint32_t bT = bBase0 + (uint32_t)((((pass == 1) ? 3 : 2) * TS_) * 2);
#pragma unroll
            for (int k16 = 0; k16 < 2; k16++) {
                uint32_t a[4][4];
#pragma unroll
                for (int mt = 0; mt < 4; mt++)
                    LDSM_X4(a[mt][0], a[mt][1], a[mt][2], a[mt][3],
                            aT + (uint32_t)(mt * 1280 + k16 * 32));
                uint32_t bf[4][2];
#pragma unroll
                for (int nt = 0; nt < 4; nt++)
                    LDSM_X2(bf[nt][0], bf[nt][1],
                            bT + (uint32_t)(nt * 640 + k16 * 32));
#pragma unroll
                for (int mt = 0; mt < 4; mt++)
#pragma unroll
                    for (int nt = 0; nt < 4; nt++)
                        MMA16816(c[mt][nt][0], c[mt][nt][1], c[mt][nt][2], c[mt][nt][3],
                                 a[mt][0], a[mt][1], a[mt][2], a[mt][3],
                                 bf[nt][0], bf[nt][1]);
            }
        }

        if (kc < 31) {
            __syncthreads();
#pragma unroll
            for (int t = 0; t < 8; t++)
                *(uint4*)((char*)smbuf + soff[t]) = pf[t];
            __syncthreads();
        }
    }

    int row_l = lane >> 2;
    int col_l = (lane & 3) * 2;
#pragma unroll
    for (int nt = 0; nt < 4; nt++) {
        int o = o0 + wn * 32 + nt * 8 + col_l;
        float bv0 = __ldg(bias + o);
        float bv1 = __ldg(bias + o + 1);
#pragma unroll
        for (int mt = 0; mt < 4; mt++) {
            int n = n0 + wm * 64 + mt * 16 + row_l;
#pragma unroll
            for (int half = 0; half < 2; half++) {
                int nn2 = n + half * 8;
                size_t idx;
                if (mode == 0) {
                    int b = nn2 >> 11, nr = nn2 & 2047;
                    int h = o >> 6,  d0 = o & 63;
                    idx = (((size_t)(b * H_ + h) * N_) + nr) * D_ + d0;
                } else {
                    idx = (size_t)nn2 * HID_ + o;
                }
                float2 vv;
                vv.x = c[mt][nt][half * 2 + 0] + bv0;
                vv.y = c[mt][nt][half * 2 + 1] + bv1;
                *(float2*)(Out + idx) = vv;
            }
        }
    }
}

// ---------------------------------------------------------------------------
// Q+K projections merged: z=0 -> Q (oscale 0.125), z=1 -> K.
// Body bit-identical to R3/R5 sgemm_nt (mode 0).
// ---------------------------------------------------------------------------
__global__ __launch_bounds__(256, 2) void sgemm_qk(
    const float* __restrict__ Xq, const float* __restrict__ Wq,
    const float* __restrict__ bq, float* __restrict__ Oq,
    const float* __restrict__ Xk, const float* __restrict__ Wk,
    const float* __restrict__ bk, float* __restrict__ Ok)
{
    const int K = HID_;
    __shared__ float As[2][8][128];
    __shared__ float Bs[2][8][128];
    int z = blockIdx.z;
    const float* X    = z ? Xk : Xq;
    const float* W    = z ? Wk : Wq;
    const float* bias = z ? bk : bq;
    float*       Out  = z ? Ok : Oq;
    float oscale      = z ? 1.0f : 0.125f;

    int tid = threadIdx.x;
    int n0 = blockIdx.y * 128;
    int o0 = blockIdx.x * 128;

    int lrow = tid >> 1;
    int lkq  = (tid & 1) * 4;
    const float* Xp = X + (size_t)(n0 + lrow) * K + lkq;
    const float* Wp = W + (size_t)(o0 + lrow) * K + lkq;

    {
        float4 xa = *(const float4*)Xp;
        float4 wa = *(const float4*)Wp;
        As[0][lkq+0][lrow] = xa.x; As[0][lkq+1][lrow] = xa.y;
        As[0][lkq+2][lrow] = xa.z; As[0][lkq+3][lrow] = xa.w;
        Bs[0][lkq+0][lrow] = wa.x; Bs[0][lkq+1][lrow] = wa.y;
        Bs[0][lkq+2][lrow] = wa.z; Bs[0][lkq+3][lrow] = wa.w;
    }
    __syncthreads();

    int tx = tid & 15, ty = tid >> 4;
    float c[8][8];
#pragma unroll
    for (int i = 0; i < 8; i++)
#pragma unroll
        for (int j = 0; j < 8; j++) c[i][j] = 0.f;

    const int NSTEP = K / 8;
#pragma unroll 2
    for (int k0 = 0; k0 < NSTEP; k0++) {
        int cur = k0 & 1;
        float4 xn, wn;
        if (k0 < NSTEP - 1) {
            xn = *(const float4*)(Xp + (k0 + 1) * 8);
            wn = *(const float4*)(Wp + (k0 + 1) * 8);
        }
#pragma unroll
        for (int kk = 0; kk < 8; kk++) {
            float a[8], b[8];
            *(float4*)&a[0] = *(const float4*)&As[cur][kk][ty*8];
            *(float4*)&a[4] = *(const float4*)&As[cur][kk][ty*8+4];
            *(float4*)&b[0] = *(const float4*)&Bs[cur][kk][tx*8];
            *(float4*)&b[4] = *(const float4*)&Bs[cur][kk][tx*8+4];
#pragma unroll
            for (int i = 0; i < 8; i++)
#pragma unroll
                for (int j = 0; j < 8; j++)
                    c[i][j] += a[i] * b[j];
        }
        if (k0 < NSTEP - 1) {
            int nxt = cur ^ 1;
            As[nxt][lkq+0][lrow] = xn.x; As[nxt][lkq+1][lrow] = xn.y;
            As[nxt][lkq+2][lrow] = xn.z; As[nxt][lkq+3][lrow] = xn.w;
            Bs[nxt][lkq+0][lrow] = wn.x; Bs[nxt][lkq+1][lrow] = wn.y;
            Bs[nxt][lkq+2][lrow] = wn.z; Bs[nxt][lkq+3][lrow] = wn.w;
            __syncthreads();
        }
    }

    float bfr[8];
#pragma unroll
    for (int j = 0; j < 8; j++) bfr[j] = __ldg(bias + o0 + tx*8 + j);

#pragma unroll
    for (int i = 0; i < 8; i++) {
        int n = n0 + ty * 8 + i;
        int o = o0 + tx * 8;
        int b = n >> 11, nn = n & 2047;
        int h = o >> 6,  d  = o & 63;
        size_t idx = (((size_t)(b * H_ + h) * N_) + nn) * D_ + d;
        float4 v0, v1;
        v0.x = (c[i][0] + bfr[0]) * oscale;
        v0.y = (c[i][1] + bfr[1]) * oscale;
        v0.z = (c[i][2] + bfr[2]) * oscale;
        v0.w = (c[i][3] + bfr[3]) * oscale;
        v1.x = (c[i][4] + bfr[4]) * oscale;
        v1.y = (c[i][5] + bfr[5]) * oscale;
        v1.z = (c[i][6] + bfr[6]) * oscale;
        v1.w = (c[i][7] + bfr[7]) * oscale;
        *(float4*)(Out + idx)     = v0;
        *(float4*)(Out + idx + 4) = v1;
    }
}

// ---------------------------------------------------------------------------
// Scores (fp32, verbatim R3/R5 -- numerics frozen)
// ---------------------------------------------------------------------------
__global__ __launch_bounds__(256, 2) void scores_kernel(void)
{
    __shared__ float Qs[32][132];
    __shared__ float Ks[32][132];
    int bh  = blockIdx.z;
    int q0  = blockIdx.y * 128;
    int kc0 = blockIdx.x * 128;
    int tid = threadIdx.x;
    const float* Qb = g_Qh + (size_t)bh * N_ * D_;
    const float* Kb = g_Kh + (size_t)bh * N_ * D_;

    int tx = tid & 15, ty = tid >> 4;
    float c[8][8];
#pragma unroll
    for (int i = 0; i < 8; i++)
#pragma unroll
        for (int j = 0; j < 8; j++) c[i][j] = 0.f;

#pragma unroll
    for (int hh = 0; hh < 2; hh++) {
#pragma unroll
        for (int l = 0; l < 4; l++) {
            int id  = tid + l * 256;
            int row = id >> 3;
            int q4  = (id & 7) * 4;
            float4 qa = *(const float4*)(Qb + (size_t)(q0  + row) * D_ + hh*32 + q4);
            float4 ka = *(const float4*)(Kb + (size_t)(kc0 + row) * D_ + hh*32 + q4);
            Qs[q4+0][row] = qa.x; Qs[q4+1][row] = qa.y;
            Qs[q4+2][row] = qa.z; Qs[q4+3][row] = qa.w;
            Ks[q4+0][row] = ka.x; Ks[q4+1][row] = ka.y;
            Ks[q4+2][row] = ka.z; Ks[q4+3][row] = ka.w;
        }
        __syncthreads();
#pragma unroll
        for (int kk = 0; kk < 32; kk++) {
            float a[8], b[8];
            *(float4*)&a[0] = *(const float4*)&Qs[kk][ty*8];
            *(float4*)&a[4] = *(const float4*)&Qs[kk][ty*8+4];
            *(float4*)&b[0] = *(const float4*)&Ks[kk][tx*8];
            *(float4*)&b[4] = *(const float4*)&Ks[kk][tx*8+4];
#pragma unroll
            for (int i = 0; i < 8; i++)
#pragma unroll
                for (int j = 0; j < 8; j++)
                    c[i][j] += a[i] * b[j];
        }
        __syncthreads();
    }

    float* Sb = g_S + (size_t)bh * N_ * N_
              + (size_t)(q0 + ty * 8) * N_ + kc0 + tx * 8;
#pragma unroll
    for (int i = 0; i < 8; i++) {
        float4 v0, v1;
        v0.x = c[i][0]; v0.y = c[i][1]; v0.z = c[i][2]; v0.w = c[i][3];
        v1.x = c[i][4]; v1.y = c[i][5]; v1.z = c[i][6]; v1.w = c[i][7];
        *(float4*)(Sb + (size_t)i * N_)     = v0;
        *(float4*)(Sb + (size_t)i * N_ + 4) = v1;
    }
}

// ---------------------------------------------------------------------------
// topk_v3: exact top-64 + softmax + PV. 4 warps/block, smem-staged row,
// scan-based compaction (no atomics), early-exit bitwise greedy.
// Selection semantics identical to R5.
// ---------------------------------------------------------------------------
__device__ __forceinline__ unsigned fflip(float f) {
    unsigned u = __float_as_uint(f);
    return (u & 0x80000000u) ? ~u : (u | 0x80000000u);
}
__device__ __forceinline__ float funflip(unsigned u) {
    unsigned v = (u & 0x80000000u) ? (u & 0x7FFFFFFFu) : ~u;
    return __uint_as_float(v);
}

#define CAP_ 320

__global__ __launch_bounds__(128) void topk_pv_kernel(void)
{
    __shared__ float          rows[4][2048];    // 32 KB
    __shared__ unsigned       candV[4][CAP_];   // 5 KB
    __shared__ unsigned short candI[4][CAP_];   // 2.5 KB
    __shared__ int   sk[4][64];
    __shared__ float sv[4][64];
    __shared__ float pw[4][64];
    __shared__ int   ek[4][64];

    int w    = threadIdx.x >> 5;
    int lane = threadIdx.x & 31;
    int gq   = blockIdx.x * 4 + w;
    int bh   = gq >> 11;
    int qr   = gq & 2047;
    unsigned ltmask = (1u << lane) - 1u;

    const float* Sb = g_S + ((size_t)bh * N_ + qr) * N_;

    // pass A: gmem -> smem, track per-lane top-2 (flipped)
    unsigned m1 = 0u, m2 = 0u;
#pragma unroll
    for (int it = 0; it < 16; it++) {
        float4 f = ((const float4*)Sb)[it * 32 + lane];
        *(float4*)&rows[w][it * 128 + lane * 4] = f;
        unsigned uu[4] = {fflip(f.x), fflip(f.y), fflip(f.z), fflip(f.w)};
#pragma unroll
        for (int r = 0; r < 4; r++) {
            unsigned x = uu[r];
            if (x > m1) { m2 = m1; m1 = x; }
            else if (x > m2) { m2 = x; }
        }
    }
    unsigned T0 = __reduce_min_sync(0xffffffffu, m2);   // >=64 values >= T0
    __syncwarp();

    // pass B: per-lane candidate count
    int cnt = 0;
#pragma unroll
    for (int it = 0; it < 16; it++) {
        float4 f = *(const float4*)&rows[w][it * 128 + lane * 4];
        cnt += (fflip(f.x) >= T0) + (fflip(f.y) >= T0)
             + (fflip(f.z) >= T0) + (fflip(f.w) >= T0);
    }
    // exclusive scan over lanes
    int off = cnt;
#pragma unroll
    for (int d = 1; d < 32; d <<= 1) {
        int t = __shfl_up_sync(0xffffffffu, off, d);
        if (lane >= d) off += t;
    }
    int nc = __shfl_sync(0xffffffffu, off, 31);
    off -= cnt;

    // pass B2: write candidates (lane-major order; deterministic)
    if (nc <= CAP_) {
        int o2 = off;
#pragma unroll
        for (int it = 0; it < 16; it++) {
            float4 f = *(const float4*)&rows[w][it * 128 + lane * 4];
            unsigned uu[4] = {fflip(f.x), fflip(f.y), fflip(f.z), fflip(f.w)};
#pragma unroll
            for (int r = 0; r < 4; r++) {
                if (uu[r] >= T0) {
                    candV[w][o2] = uu[r];
                    candI[w][o2] = (unsigned short)(it * 128 + lane * 4 + r);
                    o2++;
                }
            }
        }
    }
    __syncwarp();

    // exact 64th-largest bit pattern X (early exit when count == 64 exactly)
    unsigned X = 0u;
    if (nc <= CAP_) {
        unsigned cu[CAP_/32];
        unsigned short ci[CAP_/32];
#pragma unroll
        for (int jj = 0; jj < CAP_/32; jj++) {
            int idx = lane + jj * 32;
            cu[jj] = (idx < nc) ? candV[w][idx] : 0u;
            ci[jj] = (idx < nc) ? candI[w][idx] : 0;
        }
        unsigned t = 0u;
        for (int bit = 31; bit >= 0; bit--) {
            unsigned tt = t | (1u << bit);
            int c = 0;
#pragma unroll
            for (int jj = 0; jj < CAP_/32; jj++) c += (cu[jj] >= tt);
            c = __reduce_add_sync(0xffffffffu, c);
            if (c >= TOPK_) {
                t = tt;
                if (c == TOPK_) break;   // selected set provably identical
            }
        }
        X = t;

        // collection among candidates
        int g1 = 0, g2 = 0;
#pragma unroll
        for (int jj = 0; jj < CAP_/32; jj++) {
            int idx = lane + jj * 32;
            bool valid = (idx < nc);
            unsigned x = cu[jj];
            bool gt = valid && (x > X), eq = valid && (x == X);
            unsigned mg = __ballot_sync(0xffffffffu, gt);
            unsigned me = __ballot_sync(0xffffffffu, eq);
            if (gt) {
                int p = g1 + __popc(mg & ltmask);
                sk[w][p] = ci[jj];
                sv[w][p] = funflip(x);
            }
            if (eq) {
                int p = g2 + __popc(me & ltmask);
                if (p < 64) ek[w][p] = ci[jj];
            }
            g1 += __popc(mg);
            g2 += __popc(me);
        }
        __syncwarp();
        if (lane == 0) {
            int need = TOPK_ - g1;
            int ec   = g2 > 64 ? 64 : g2;
            float xv = funflip(X);
            for (int s2 = 0; s2 < need; s2++) {
                int best = 0x7FFFFFFF, bi = 0;
                for (int e = 0; e < ec; e++) {
                    int v2 = ek[w][e];
                    if (v2 < best) { best = v2; bi = e; }
                }
                ek[w][bi] = 0x7FFFFFFF;
                sk[w][g1 + s2] = best;
                sv[w][g1 + s2] = xv;
            }
        }
    } else {
        // slow fallback (prob ~0): full greedy + collection from smem rows
        unsigned t = 0u;
        for (int bit = 31; bit >= 0; bit--) {
            unsigned tt = t | (1u << bit);
            int c = 0;
            for (int it = 0; it < 16; it++) {
                float4 f = *(const float4*)&rows[w][it * 128 + lane * 4];
                c += (fflip(f.x) >= tt) + (fflip(f.y) >= tt)
                   + (fflip(f.z) >= tt) + (fflip(f.w) >= tt);
            }
            c = __reduce_add_sync(0xffffffffu, c);
            if (c >= TOPK_) {
                t = tt;
                if (c == TOPK_) break;
            }
        }
        X = t;
        int g1 = 0, g2 = 0;
        for (int it = 0; it < 16; it++) {
            float4 f = *(const float4*)&rows[w][it * 128 + lane * 4];
            unsigned uu[4] = {fflip(f.x), fflip(f.y), fflip(f.z), fflip(f.w)};
#pragma unroll
            for (int r = 0; r < 4; r++) {
                unsigned x = uu[r];
                int kix = it * 128 + lane * 4 + r;
                bool gt = (x > X), eq = (x == X);
                unsigned mg = __ballot_sync(0xffffffffu, gt);
                unsigned me = __ballot_sync(0xffffffffu, eq);
                if (gt) {
                    int p = g1 + __popc(mg & ltmask);
                    sk[w][p] = kix;
                    sv[w][p] = funflip(x);
                }
                if (eq) {
                    int p = g2 + __popc(me & ltmask);
                    if (p < 64) ek[w][p] = kix;
                }
                g1 += __popc(mg);
                g2 += __popc(me);
            }
        }
        __syncwarp();
        if (lane == 0) {
            int need = TOPK_ - g1;
            int ec   = g2 > 64 ? 64 : g2;
            float xv = funflip(X);
            for (int s2 = 0; s2 < need; s2++) {
                int best = 0x7FFFFFFF, bi = 0;
                for (int e = 0; e < ec; e++) {
                    int v2 = ek[w][e];
                    if (v2 < best) { best = v2; bi = e; }
                }
                ek[w][bi] = 0x7FFFFFFF;
                sk[w][g1 + s2] = best;
                sv[w][g1 + s2] = xv;
            }
        }
    }
    __syncwarp();

    // softmax over selected 64
    float v0 = sv[w][lane];
    float v1 = sv[w][lane + 32];
    float mx = funflip(__reduce_max_sync(0xffffffffu,
                 (unsigned)max(fflip(v0), fflip(v1))));
    float p0 = expf(v0 - mx);
    float p1 = expf(v1 - mx);
    pw[w][lane]      = p0;
    pw[w][lane + 32] = p1;
    float z = p0 + p1;
#pragma unroll
    for (int offx = 16; offx > 0; offx >>= 1)
        z += __shfl_xor_sync(0xffffffffu, z, offx);
    float invZ = 1.0f / z;

    // PV
    const float* Vb = g_Vh + (size_t)bh * N_ * D_;
    float acc0 = 0.f, acc1 = 0.f;
#pragma unroll 8
    for (int j = 0; j < 64; j++) {
        float p  = pw[w][j];
        int   kj = sk[w][j];
        acc0 += p * __ldg(Vb + (size_t)kj * D_ + lane);
        acc1 += p * __ldg(Vb + (size_t)kj * D_ + lane + 32);
    }

    int b = bh >> 4, h = bh & 15;
    size_t obase = ((size_t)(b * N_ + qr)) * HID_ + h * D_ + lane;
    g_ctx[obase]      = acc0 * invZ;
    g_ctx[obase + 32] = acc1 * invZ;
}

// ---------------------------------------------------------------------------
extern "C" void kernel_launch(void* const* d_in, const int* in_sizes, int n_in,
                              void* d_out, int out_size)
{
    const float* q    = (const float*)d_in[0];
    const float* k    = (const float*)d_in[1];
    const float* v    = (const float*)d_in[2];
    const float* wq_w = (const float*)d_in[5];
    const float* wq_b = (const float*)d_in[6];
    const float* wk_w = (const float*)d_in[7];
    const float* wk_b = (const float*)d_in[8];
    const float* wv_w = (const float*)d_in[9];
    const float* wv_b = (const float*)d_in[10];
    const float* wo_w = (const float*)d_in[11];
    const float* wo_b = (const float*)d_in[12];
    float* out = (float*)d_out;

    float *Qh, *Kh, *Vh, *ctx;
    __nv_bfloat16 *Vxhi, *Vxlo, *Whi, *Wlo, *Chi, *Clo;
    cudaGetSymbolAddress((void**)&Qh,   g_Qh);
    cudaGetSymbolAddress((void**)&Kh,   g_Kh);
    cudaGetSymbolAddress((void**)&Vh,   g_Vh);
    cudaGetSymbolAddress((void**)&ctx,  g_ctx);
    cudaGetSymbolAddress((void**)&Vxhi, g_Vxhi);
    cudaGetSymbolAddress((void**)&Vxlo, g_Vxlo);
    cudaGetSymbolAddress((void**)&Whi,  g_Whi);
    cudaGetSymbolAddress((void**)&Wlo,  g_Wlo);
    cudaGetSymbolAddress((void**)&Chi,  g_Chi);
    cudaGetSymbolAddress((void**)&Clo,  g_Clo);

    const int NX4 = B_ * N_ * HID_ / 4;
    const int NW4 = HID_ * HID_ / 4;

    split_kernel<<<NX4/256, 256>>>(v,    Vxhi, Vxlo, NX4);
    split_kernel<<<NW4/256, 256>>>(wv_w, Whi,             Wlo,             NW4);
    split_kernel<<<NW4/256, 256>>>(wo_w, Whi + HID_*HID_, Wlo + HID_*HID_, NW4);

    dim3 gQK(HID_ / 128, (B_ * N_) / 128, 2);   // 8 x 32 x 2
    sgemm_qk<<<gQK, 256>>>(q, wq_w, wq_b, Qh, k, wk_w, wk_b, Kh);

    dim3 gProj(HID_ / 128, (B_ * N_) / 128);    // 8 x 32
    hmma_gemm<<<gProj, 256>>>(Vxhi, Vxlo, Whi, Wlo, wv_b, Vh, 0);

    dim3 gSc(N_ / 128, N_ / 128, BH_);          // 16 x 16 x 32
    scores_kernel<<<gSc, 256>>>();

    topk_pv_kernel<<<(B_ * N_ * H_) / 4, 128>>>();   // 16384 blocks

    split_kernel<<<NX4/256, 256>>>(ctx, Chi, Clo, NX4);
    hmma_gemm<<<gProj, 256>>>(Chi, Clo, Whi + HID_*HID_, Wlo + HID_*HID_,
                              wo_b, out, 1);
}

// round 10
// speedup vs baseline: 1.3347x; 1.0344x over previous
#include <cuda_runtime.h>
#include <cuda_bf16.h>
#include <cstdint>
#include <cstddef>
#include <math.h>

#define B_   2
#define N_   2048
#define HID_ 1024
#define H_   16
#define D_   64
#define BH_  (B_*H_)     // 32
#define M_   (B_*N_)     // 4096
#define TOPK_ 64

// fp32 scratch
__device__ float g_Qh[BH_*N_*D_];             // [bh][n][d] (pre-scaled 0.125)
__device__ float g_Kh[BH_*N_*D_];
__device__ float g_Vh[BH_*N_*D_];
__device__ float g_S[134217728];              // 537 MB [bh][q][k]
__device__ float g_ctx[M_*HID_];

// bf16 split scratch (V path + O path)
__device__ __nv_bfloat16 g_Vxhi[M_*HID_];
__device__ __nv_bfloat16 g_Vxlo[M_*HID_];
__device__ __nv_bfloat16 g_Whi[2*HID_*HID_];  // wv, wo
__device__ __nv_bfloat16 g_Wlo[2*HID_*HID_];
__device__ __nv_bfloat16 g_Chi[M_*HID_];
__device__ __nv_bfloat16 g_Clo[M_*HID_];

// 3-term splits of Qh / Kh for tensor-core scores (h/m/l each)
__device__ __nv_bfloat16 g_Q3[3][BH_*N_*D_];
__device__ __nv_bfloat16 g_K3[3][BH_*N_*D_];

// ---------------------------------------------------------------------------
#define LDSM_X4(r0,r1,r2,r3,addr) \
    asm volatile("ldmatrix.sync.aligned.m8n8.x4.shared.b16 {%0,%1,%2,%3}, [%4];" \
        : "=r"(r0), "=r"(r1), "=r"(r2), "=r"(r3) : "r"(addr))
#define LDSM_X2(r0,r1,addr) \
    asm volatile("ldmatrix.sync.aligned.m8n8.x2.shared.b16 {%0,%1}, [%2];" \
        : "=r"(r0), "=r"(r1) : "r"(addr))
#define MMA16816(c0,c1,c2,c3,a0,a1,a2,a3,b0,b1) \
    asm volatile("mma.sync.aligned.m16n8k16.row.col.f32.bf16.bf16.f32 " \
        "{%0,%1,%2,%3}, {%4,%5,%6,%7}, {%8,%9}, {%0,%1,%2,%3};" \
        : "+f"(c0), "+f"(c1), "+f"(c2), "+f"(c3) \
        : "r"(a0), "r"(a1), "r"(a2), "r"(a3), "r"(b0), "r"(b1))

__device__ __forceinline__ uint32_t smem_u32(const void* p) {
    uint32_t a;
    asm("{ .reg .u64 t; cvta.to.shared.u64 t, %1; cvt.u32.u64 %0, t; }"
        : "=r"(a) : "l"(p));
    return a;
}

// ---------------------------------------------------------------------------
// Split fp32 -> bf16 hi + lo (2-term, V/O path)
// ---------------------------------------------------------------------------
__global__ __launch_bounds__(256) void split_kernel(
    const float* __restrict__ src, __nv_bfloat16* __restrict__ hi,
    __nv_bfloat16* __restrict__ lo, int n4)
{
    int i = blockIdx.x * 256 + threadIdx.x;
    if (i >= n4) return;
    float4 x = ((const float4*)src)[i];
    __nv_bfloat16 h0 = __float2bfloat16_rn(x.x);
    __nv_bfloat16 h1 = __float2bfloat16_rn(x.y);
    __nv_bfloat16 h2 = __float2bfloat16_rn(x.z);
    __nv_bfloat16 h3 = __float2bfloat16_rn(x.w);
    __nv_bfloat16 l0 = __float2bfloat16_rn(x.x - __bfloat162float(h0));
    __nv_bfloat16 l1 = __float2bfloat16_rn(x.y - __bfloat162float(h1));
    __nv_bfloat16 l2 = __float2bfloat16_rn(x.z - __bfloat162float(h2));
    __nv_bfloat16 l3 = __float2bfloat16_rn(x.w - __bfloat162float(h3));
    __nv_bfloat162 a, b, c, d;
    a.x = h0; a.y = h1; b.x = h2; b.y = h3;
    c.x = l0; c.y = l1; d.x = l2; d.y = l3;
    ((__nv_bfloat162*)hi)[2*i]   = a;
    ((__nv_bfloat162*)hi)[2*i+1] = b;
    ((__nv_bfloat162*)lo)[2*i]   = c;
    ((__nv_bfloat162*)lo)[2*i+1] = d;
}

// Split fp32 -> bf16 h + m + l (3-term, scores path)
__global__ __launch_bounds__(256) void split3_kernel(
    const float* __restrict__ src,
    __nv_bfloat16* __restrict__ h, __nv_bfloat16* __restrict__ m,
    __nv_bfloat16* __restrict__ l, int n)
{
    int i = blockIdx.x * 256 + threadIdx.x;
    if (i >= n) return;
    float x = src[i];
    __nv_bfloat16 hh = __float2bfloat16_rn(x);
    float r1 = x - __bfloat162float(hh);
    __nv_bfloat16 mm = __float2bfloat16_rn(r1);
    float r2 = r1 - __bfloat162float(mm);
    __nv_bfloat16 ll = __float2bfloat16_rn(r2);
    h[i] = hh; m[i] = mm; l[i] = ll;
}

// ---------------------------------------------------------------------------
// HMMA split-bf16 GEMM (verbatim R5) - V and O projections
// ---------------------------------------------------------------------------
#define TS_   5120          // tile size in bf16 (128 rows * 40)

__global__ __launch_bounds__(256, 2) void hmma_gemm(
    const __nv_bfloat16* __restrict__ Ahi, const __nv_bfloat16* __restrict__ Alo,
    const __nv_bfloat16* __restrict__ Bhi, const __nv_bfloat16* __restrict__ Blo,
    const float* __restrict__ bias, float* __restrict__ Out, int mode)
{
    __shared__ __align__(16) __nv_bfloat16 smbuf[4 * TS_];   // 40960 B
    int tid  = threadIdx.x;
    int wid  = tid >> 5, lane = tid & 31;
    int wm   = wid >> 2;
    int wn   = wid & 3;
    int o0   = blockIdx.x * 128;
    int n0   = blockIdx.y * 128;

    uint32_t smb = smem_u32(smbuf);

    float c[4][4][4];
#pragma unroll
    for (int mt = 0; mt < 4; mt++)
#pragma unroll
        for (int nt = 0; nt < 4; nt++)
#pragma unroll
            for (int r = 0; r < 4; r++) c[mt][nt][r] = 0.f;

    int rowm[8], segm[8];
    const __nv_bfloat16* gbase[8];
#pragma unroll
    for (int t = 0; t < 8; t++) {
        int tile = t >> 1;
        int sub  = ((t & 1) << 8) + tid;
        rowm[t] = sub >> 2; segm[t] = sub & 3;
        const __nv_bfloat16* base =
            (tile == 0) ? Ahi : (tile == 1) ? Alo : (tile == 2) ? Bhi : Blo;
        int grow = (tile < 2) ? (n0 + rowm[t]) : (o0 + rowm[t]);
        gbase[t] = base + (size_t)grow * HID_ + segm[t] * 8;
    }
    uint32_t soff[8];
#pragma unroll
    for (int t = 0; t < 8; t++)
        soff[t] = (uint32_t)(((t >> 1) * TS_ + rowm[t] * 40 + segm[t] * 8) * 2);

    uint32_t laneA = (uint32_t)((lane & 15) * 80 + (lane >> 4) * 16);
    uint32_t laneB = (uint32_t)((lane & 7) * 80 + ((lane >> 3) & 1) * 16);
    uint32_t aBase0 = smb + (uint32_t)(wm * 64 * 80) + laneA;
    uint32_t bBase0 = smb + (uint32_t)(wn * 32 * 80) + laneB;

    uint4 pf[8];
#pragma unroll
    for (int t = 0; t < 8; t++) pf[t] = *(const uint4*)gbase[t];
#pragma unroll
    for (int t = 0; t < 8; t++) *(uint4*)((char*)smbuf + soff[t]) = pf[t];
    __syncthreads();

    for (int kc = 0; kc < 32; kc++) {
        if (kc < 31) {
#pragma unroll
            for (int t = 0; t < 8; t++)
                pf[t] = *(const uint4*)(gbase[t] + (kc + 1) * 32);
        }

#pragma unroll
        for (int pass = 0; pass < 3; pass++) {
            uint32_t aT = aBase0 + (uint32_t)(((pass == 2) ? TS_ : 0) * 2);
            uint32_t bT = bBase0 + (uint32_t)((((pass == 1) ? 3 : 2) * TS_) * 2);
#pragma unroll
            for (int k16 = 0; k16 < 2; k16++) {
                uint32_t a[4][4];
#pragma unroll
                for (int mt = 0; mt < 4; mt++)
                    LDSM_X4(a[mt][0], a[mt][1], a[mt][2], a[mt][3],
                            aT + (uint32_t)(mt * 1280 + k16 * 32));
                uint32_t bf[4][2];
#pragma unroll
                for (int nt = 0; nt < 4; nt++)
                    LDSM_X2(bf[nt][0], bf[nt][1],
                            bT + (uint32_t)(nt * 640 + k16 * 32));
#pragma unroll
                for (int mt = 0; mt < 4; mt++)
#pragma unroll
                    for (int nt = 0; nt < 4; nt++)
                        MMA16816(c[mt][nt][0], c[mt][nt][1], c[mt][nt][2], c[mt][nt][3],
                                 a[mt][0], a[mt][1], a[mt][2], a[mt][3],
                                 bf[nt][0], bf[nt][1]);
            }
        }

        if (kc < 31) {
            __syncthreads();
#pragma unroll
            for (int t = 0; t < 8; t++)
                *(uint4*)((char*)smbuf + soff[t]) = pf[t];
            __syncthreads();
        }
    }

    int row_l = lane >> 2;
    int col_l = (lane & 3) * 2;
#pragma unroll
    for (int nt = 0; nt < 4; nt++) {
        int o = o0 + wn * 32 + nt * 8 + col_l;
        float bv0 = __ldg(bias + o);
        float bv1 = __ldg(bias + o + 1);
#pragma unroll
        for (int mt = 0; mt < 4; mt++) {
            int n = n0 + wm * 64 + mt * 16 + row_l;
#pragma unroll
            for (int half = 0; half < 2; half++) {
                int nn2 = n + half * 8;
                size_t idx;
                if (mode == 0) {
                    int b = nn2 >> 11, nr = nn2 & 2047;
                    int h = o >> 6,  d0 = o & 63;
                    idx = (((size_t)(b * H_ + h) * N_) + nr) * D_ + d0;
                } else {
                    idx = (size_t)nn2 * HID_ + o;
                }
                float2 vv;
                vv.x = c[mt][nt][half * 2 + 0] + bv0;
                vv.y = c[mt][nt][half * 2 + 1] + bv1;
                *(float2*)(Out + idx) = vv;
            }
        }
    }
}

// ---------------------------------------------------------------------------
// Q+K projections merged (verbatim R7, fp32 exact -- numerics frozen)
// ---------------------------------------------------------------------------
__global__ __launch_bounds__(256, 2) void sgemm_qk(
    const float* __restrict__ Xq, const float* __restrict__ Wq,
    const float* __restrict__ bq, float* __restrict__ Oq,
    const float* __restrict__ Xk, const float* __restrict__ Wk,
    const float* __restrict__ bk, float* __restrict__ Ok)
{
    const int K = HID_;
    __shared__ float As[2][8][128];
    __shared__ float Bs[2][8][128];
    int z = blockIdx.z;
    const float* X    = z ? Xk : Xq;
    const float* W    = z ? Wk : Wq;
    const float* bias = z ? bk : bq;
    float*       Out  = z ? Ok : Oq;
    float oscale      = z ? 1.0f : 0.125f;

    int tid = threadIdx.x;
    int n0 = blockIdx.y * 128;
    int o0 = blockIdx.x * 128;

    int lrow = tid >> 1;
    int lkq  = (tid & 1) * 4;
    const float* Xp = X + (size_t)(n0 + lrow) * K + lkq;
    const float* Wp = W + (size_t)(o0 + lrow) * K + lkq;

    {
        float4 xa = *(const float4*)Xp;
        float4 wa = *(const float4*)Wp;
        As[0][lkq+0][lrow] = xa.x; As[0][lkq+1][lrow] = xa.y;
        As[0][lkq+2][lrow] = xa.z; As[0][lkq+3][lrow] = xa.w;
        Bs[0][lkq+0][lrow] = wa.x; Bs[0][lkq+1][lrow] = wa.y;
        Bs[0][lkq+2][lrow] = wa.z; Bs[0][lkq+3][lrow] = wa.w;
    }
    __syncthreads();

    int tx = tid & 15, ty = tid >> 4;
    float c[8][8];
#pragma unroll
    for (int i = 0; i < 8; i++)
#pragma unroll
        for (int j = 0; j < 8; j++) c[i][j] = 0.f;

    const int NSTEP = K / 8;
#pragma unroll 2
    for (int k0 = 0; k0 < NSTEP; k0++) {
        int cur = k0 & 1;
        float4 xn, wn;
        if (k0 < NSTEP - 1) {
            xn = *(const float4*)(Xp + (k0 + 1) * 8);
            wn = *(const float4*)(Wp + (k0 + 1) * 8);
        }
#pragma unroll
        for (int kk = 0; kk < 8; kk++) {
            float a[8], b[8];
            *(float4*)&a[0] = *(const float4*)&As[cur][kk][ty*8];
            *(float4*)&a[4] = *(const float4*)&As[cur][kk][ty*8+4];
            *(float4*)&b[0] = *(const float4*)&Bs[cur][kk][tx*8];
            *(float4*)&b[4] = *(const float4*)&Bs[cur][kk][tx*8+4];
#pragma unroll
            for (int i = 0; i < 8; i++)
#pragma unroll
                for (int j = 0; j < 8; j++)
                    c[i][j] += a[i] * b[j];
        }
        if (k0 < NSTEP - 1) {
            int nxt = cur ^ 1;
            As[nxt][lkq+0][lrow] = xn.x; As[nxt][lkq+1][lrow] = xn.y;
            As[nxt][lkq+2][lrow] = xn.z; As[nxt][lkq+3][lrow] = xn.w;
            Bs[nxt][lkq+0][lrow] = wn.x; Bs[nxt][lkq+1][lrow] = wn.y;
            Bs[nxt][lkq+2][lrow] = wn.z; Bs[nxt][lkq+3][lrow] = wn.w;
            __syncthreads();
        }
    }

    float bfr[8];
#pragma unroll
    for (int j = 0; j < 8; j++) bfr[j] = __ldg(bias + o0 + tx*8 + j);

#pragma unroll
    for (int i = 0; i < 8; i++) {
        int n = n0 + ty * 8 + i;
        int o = o0 + tx * 8;
        int b = n >> 11, nn = n & 2047;
        int h = o >> 6,  d  = o & 63;
        size_t idx = (((size_t)(b * H_ + h) * N_) + nn) * D_ + d;
        float4 v0, v1;
        v0.x = (c[i][0] + bfr[0]) * oscale;
        v0.y = (c[i][1] + bfr[1]) * oscale;
        v0.z = (c[i][2] + bfr[2]) * oscale;
        v0.w = (c[i][3] + bfr[3]) * oscale;
        v1.x = (c[i][4] + bfr[4]) * oscale;
        v1.y = (c[i][5] + bfr[5]) * oscale;
        v1.z = (c[i][6] + bfr[6]) * oscale;
        v1.w = (c[i][7] + bfr[7]) * oscale;
        *(float4*)(Out + idx)     = v0;
        *(float4*)(Out + idx + 4) = v1;
    }
}

// ---------------------------------------------------------------------------
// Scores via 3-term split bf16 HMMA (6 passes: hh, hm, mh, hl, lh, mm).
// Per-score error ~1e-6 relative (fp32-chain comparable). 128x128 tile, K=64.
// ---------------------------------------------------------------------------
__constant__ int c_passA[6] = {0, 0, 1, 0, 2, 1};
__constant__ int c_passB[6] = {3, 4, 3, 5, 3, 4};

__global__ __launch_bounds__(256, 2) void scores_s3(void)
{
    __shared__ __align__(16) __nv_bfloat16 smbuf[6 * TS_];   // 61440 B? no: 6*5120*2 = 61440 B
    // NOTE: 61440 B exceeds 48KB static limit -> use 32-col tiles: TS stays 5120
    // entries but only 6 tiles => 61440 bytes. Instead we use half-size tiles:
    // rows*40 entries with 32 cols valid is already the layout; cannot shrink.
    // Fallback: process splits in two tile-groups of 3 (see below).
    int dummy = 0; (void)dummy;
    // -- this kernel body replaced below by grouped version --
}

// Grouped version: smem holds Q-tile group (3 splits) + 1 K split at a time?
// Simpler correct approach: 4-tile buffer (40KB static), 2 rounds per kc:
//   round 0: tiles {Qh, Qm, Kh, Km} -> passes hh, hm, mh, mm
//   round 1: tiles {Qh, Ql, Kh, Kl} -> passes hl, lh
__global__ __launch_bounds__(256, 2) void scores_s3g(void)
{
    __shared__ __align__(16) __nv_bfloat16 smbuf[4 * TS_];   // 40960 B
    int tid  = threadIdx.x;
    int wid  = tid >> 5, lane = tid & 31;
    int wm   = wid >> 2;
    int wn   = wid & 3;
    int bh   = blockIdx.z;
    int k0   = blockIdx.x * 128;
    int q0   = blockIdx.y * 128;

    uint32_t smb = smem_u32(smbuf);

    const __nv_bfloat16* Qs[3] = {
        g_Q3[0] + (size_t)bh * N_ * D_,
        g_Q3[1] + (size_t)bh * N_ * D_,
        g_Q3[2] + (size_t)bh * N_ * D_ };
    const __nv_bfloat16* Ks[3] = {
        g_K3[0] + (size_t)bh * N_ * D_,
        g_K3[1] + (size_t)bh * N_ * D_,
        g_K3[2] + (size_t)bh * N_ * D_ };

    float c[4][4][4];
#pragma unroll
    for (int mt = 0; mt < 4; mt++)
#pragma unroll
        for (int nt = 0; nt < 4; nt++)
#pragma unroll
            for (int r = 0; r < 4; r++) c[mt][nt][r] = 0.f;

    uint32_t laneA = (uint32_t)((lane & 15) * 80 + (lane >> 4) * 16);
    uint32_t laneB = (uint32_t)((lane & 7) * 80 + ((lane >> 3) & 1) * 16);
    uint32_t aBase0 = smb + (uint32_t)(wm * 64 * 80) + laneA;
    uint32_t bBase0 = smb + (uint32_t)(wn * 32 * 80) + laneB;

    // round r: tile slots {0:Qh, 1:Q[r+1], 2:Kh, 3:K[r+1]}
    //   passes round0: (0,2)=hh (0,3)=hm (1,2)=mh (1,3)=mm
    //   passes round1: (0,3)=hl (1,2)=lh
#pragma unroll
    for (int rnd = 0; rnd < 2; rnd++) {
#pragma unroll
        for (int kc = 0; kc < 2; kc++) {
            if (rnd || kc) __syncthreads();   // protect previous tiles
            // load 4 tiles of 128 rows x 32 cols
#pragma unroll
            for (int t = 0; t < 8; t++) {
                int tile = t >> 1;
                int sub  = ((t & 1) << 8) + tid;
                int row  = sub >> 2, seg = sub & 3;
                const __nv_bfloat16* base =
                    (tile == 0) ? Qs[0] : (tile == 1) ? Qs[rnd + 1]
                  : (tile == 2) ? Ks[0] : Ks[rnd + 1];
                const __nv_bfloat16* src =
                    base + (size_t)(((tile < 2) ? q0 : k0) + row) * D_
                         + kc * 32 + seg * 8;
                *(uint4*)((char*)smbuf + (tile * TS_ + row * 40 + seg * 8) * 2) =
                    *(const uint4*)src;
            }
            __syncthreads();

            int npass = rnd ? 2 : 4;
            for (int p = 0; p < npass; p++) {
                // round0 pairs: (0,2),(0,3),(1,2),(1,3); round1: (0,3),(1,2)
                int at, bt;
                if (rnd == 0) { at = p >> 1; bt = 2 + (p & 1); }
                else          { at = p;      bt = 3 - p; }
                uint32_t aT = aBase0 + (uint32_t)(at * TS_ * 2);
                uint32_t bT = bBase0 + (uint32_t)(bt * TS_ * 2);
#pragma unroll
                for (int k16 = 0; k16 < 2; k16++) {
                    uint32_t a[4][4];
#pragma unroll
                    for (int mt = 0; mt < 4; mt++)
                        LDSM_X4(a[mt][0], a[mt][1], a[mt][2], a[mt][3],
                                aT + (uint32_t)(mt * 1280 + k16 * 32));
                    uint32_t bf[4][2];
#pragma unroll
                    for (int nt = 0; nt < 4; nt++)
                        LDSM_X2(bf[nt][0], bf[nt][1],
                                bT + (uint32_t)(nt * 640 + k16 * 32));
#pragma unroll
                    for (int mt = 0; mt < 4; mt++)
#pragma unroll
                        for (int nt = 0; nt < 4; nt++)
                            MMA16816(c[mt][nt][0], c[mt][nt][1], c[mt][nt][2], c[mt][nt][3],
                                     a[mt][0], a[mt][1], a[mt][2], a[mt][3],
                                     bf[nt][0], bf[nt][1]);
                }
            }
        }
    }

    int row_l = lane >> 2;
    int col_l = (lane & 3) * 2;
    float* Sb = g_S + (size_t)bh * N_ * N_;
#pragma unroll
    for (int nt = 0; nt < 4; nt++) {
        int o = k0 + wn * 32 + nt * 8 + col_l;
#pragma unroll
        for (int mt = 0; mt < 4; mt++) {
            int n = q0 + wm * 64 + mt * 16 + row_l;
#pragma unroll
            for (int half = 0; half < 2; half++) {
                int qq = n + half * 8;
                float2 vv;
                vv.x = c[mt][nt][half * 2 + 0];
                vv.y = c[mt][nt][half * 2 + 1];
                *(float2*)(Sb + (size_t)qq * N_ + o) = vv;
            }
        }
    }
}

// ---------------------------------------------------------------------------
// topk_v3 (verbatim R7): exact top-64 + softmax + PV.
// ---------------------------------------------------------------------------
__device__ __forceinline__ unsigned fflip(float f) {
    unsigned u = __float_as_uint(f);
    return (u & 0x80000000u) ? ~u : (u | 0x80000000u);
}
__device__ __forceinline__ float funflip(unsigned u) {
    unsigned v = (u & 0x80000000u) ? (u & 0x7FFFFFFFu) : ~u;
    return __uint_as_float(v);
}

#define CAP_ 320

__global__ __launch_bounds__(128) void topk_pv_kernel(void)
{
    __shared__ float          rows[4][2048];
    __shared__ unsigned       candV[4][CAP_];
    __shared__ unsigned short candI[4][CAP_];
    __shared__ int   sk[4][64];
    __shared__ float sv[4][64];
    __shared__ float pw[4][64];
    __shared__ int   ek[4][64];

    int w    = threadIdx.x >> 5;
    int lane = threadIdx.x & 31;
    int gq   = blockIdx.x * 4 + w;
    int bh   = gq >> 11;
    int qr   = gq & 2047;
    unsigned ltmask = (1u << lane) - 1u;

    const float* Sb = g_S + ((size_t)bh * N_ + qr) * N_;

    unsigned m1 = 0u, m2 = 0u;
#pragma unroll
    for (int it = 0; it < 16; it++) {
        float4 f = ((const float4*)Sb)[it * 32 + lane];
        *(float4*)&rows[w][it * 128 + lane * 4] = f;
        unsigned uu[4] = {fflip(f.x), fflip(f.y), fflip(f.z), fflip(f.w)};
#pragma unroll
        for (int r = 0; r < 4; r++) {
            unsigned x = uu[r];
            if (x > m1) { m2 = m1; m1 = x; }
            else if (x > m2) { m2 = x; }
        }
    }
    unsigned T0 = __reduce_min_sync(0xffffffffu, m2);
    __syncwarp();

    int cnt = 0;
#pragma unroll
    for (int it = 0; it < 16; it++) {
        float4 f = *(const float4*)&rows[w][it * 128 + lane * 4];
        cnt += (fflip(f.x) >= T0) + (fflip(f.y) >= T0)
             + (fflip(f.z) >= T0) + (fflip(f.w) >= T0);
    }
    int off = cnt;
#pragma unroll
    for (int d = 1; d < 32; d <<= 1) {
        int t = __shfl_up_sync(0xffffffffu, off, d);
        if (lane >= d) off += t;
    }
    int nc = __shfl_sync(0xffffffffu, off, 31);
    off -= cnt;

    if (nc <= CAP_) {
        int o2 = off;
#pragma unroll
        for (int it = 0; it < 16; it++) {
            float4 f = *(const float4*)&rows[w][it * 128 + lane * 4];
            unsigned uu[4] = {fflip(f.x), fflip(f.y), fflip(f.z), fflip(f.w)};
#pragma unroll
            for (int r = 0; r < 4; r++) {
                if (uu[r] >= T0) {
                    candV[w][o2] = uu[r];
                    candI[w][o2] = (unsigned short)(it * 128 + lane * 4 + r);
                    o2++;
                }
            }
        }
    }
    __syncwarp();

    unsigned X = 0u;
    if (nc <= CAP_) {
        unsigned cu[CAP_/32];
        unsigned short ci[CAP_/32];
#pragma unroll
        for (int jj = 0; jj < CAP_/32; jj++) {
            int idx = lane + jj * 32;
            cu[jj] = (idx < nc) ? candV[w][idx] : 0u;
            ci[jj] = (idx < nc) ? candI[w][idx] : 0;
        }
        unsigned t = 0u;
        for (int bit = 31; bit >= 0; bit--) {
            unsigned tt = t | (1u << bit);
            int c = 0;
#pragma unroll
            for (int jj = 0; jj < CAP_/32; jj++) c += (cu[jj] >= tt);
            c = __reduce_add_sync(0xffffffffu, c);
            if (c >= TOPK_) {
                t = tt;
                if (c == TOPK_) break;
            }
        }
        X = t;

        int g1 = 0, g2 = 0;
#pragma unroll
        for (int jj = 0; jj < CAP_/32; jj++) {
            int idx = lane + jj * 32;
            bool valid = (idx < nc);
            unsigned x = cu[jj];
            bool gt = valid && (x > X), eq = valid && (x == X);
            unsigned mg = __ballot_sync(0xffffffffu, gt);
            unsigned me = __ballot_sync(0xffffffffu, eq);
            if (gt) {
                int p = g1 + __popc(mg & ltmask);
                sk[w][p] = ci[jj];
                sv[w][p] = funflip(x);
            }
            if (eq) {
                int p = g2 + __popc(me & ltmask);
                if (p < 64) ek[w][p] = ci[jj];
            }
            g1 += __popc(mg);
            g2 += __popc(me);
        }
        __syncwarp();
        if (lane == 0) {
            int need = TOPK_ - g1;
            int ec   = g2 > 64 ? 64 : g2;
            float xv = funflip(X);
            for (int s2 = 0; s2 < need; s2++) {
                int best = 0x7FFFFFFF, bi = 0;
                for (int e = 0; e < ec; e++) {
                    int v2 = ek[w][e];
                    if (v2 < best) { best = v2; bi = e; }
                }
                ek[w][bi] = 0x7FFFFFFF;
                sk[w][g1 + s2] = best;
                sv[w][g1 + s2] = xv;
            }
        }
    } else {
        unsigned t = 0u;
        for (int bit = 31; bit >= 0; bit--) {
            unsigned tt = t | (1u << bit);
            int c = 0;
            for (int it = 0; it < 16; it++) {
                float4 f = *(const float4*)&rows[w][it * 128 + lane * 4];
                c += (fflip(f.x) >= tt) + (fflip(f.y) >= tt)
                   + (fflip(f.z) >= tt) + (fflip(f.w) >= tt);
            }
            c = __reduce_add_sync(0xffffffffu, c);
            if (c >= TOPK_) {
                t = tt;
                if (c == TOPK_) break;
            }
        }
        X = t;
        int g1 = 0, g2 = 0;
        for (int it = 0; it < 16; it++) {
            float4 f = *(const float4*)&rows[w][it * 128 + lane * 4];
            unsigned uu[4] = {fflip(f.x), fflip(f.y), fflip(f.z), fflip(f.w)};
#pragma unroll
            for (int r = 0; r < 4; r++) {
                unsigned x = uu[r];
                int kix = it * 128 + lane * 4 + r;
                bool gt = (x > X), eq = (x == X);
                unsigned mg = __ballot_sync(0xffffffffu, gt);
                unsigned me = __ballot_sync(0xffffffffu, eq);
                if (gt) {
                    int p = g1 + __popc(mg & ltmask);
                    sk[w][p] = kix;
                    sv[w][p] = funflip(x);
                }
                if (eq) {
                    int p = g2 + __popc(me & ltmask);
                    if (p < 64) ek[w][p] = kix;
                }
                g1 += __popc(mg);
                g2 += __popc(me);
            }
        }
        __syncwarp();
        if (lane == 0) {
            int need = TOPK_ - g1;
            int ec   = g2 > 64 ? 64 : g2;
            float xv = funflip(X);
            for (int s2 = 0; s2 < need; s2++) {
                int best = 0x7FFFFFFF, bi = 0;
                for (int e = 0; e < ec; e++) {
                    int v2 = ek[w][e];
                    if (v2 < best) { best = v2; bi = e; }
                }
                ek[w][bi] = 0x7FFFFFFF;
                sk[w][g1 + s2] = best;
                sv[w][g1 + s2] = xv;
            }
        }
    }
    __syncwarp();

    float v0 = sv[w][lane];
    float v1 = sv[w][lane + 32];
    float mx = funflip(__reduce_max_sync(0xffffffffu,
                 (unsigned)max(fflip(v0), fflip(v1))));
    float p0 = expf(v0 - mx);
    float p1 = expf(v1 - mx);
    pw[w][lane]      = p0;
    pw[w][lane + 32] = p1;
    float z = p0 + p1;
#pragma unroll
    for (int offx = 16; offx > 0; offx >>= 1)
        z += __shfl_xor_sync(0xffffffffu, z, offx);
    float invZ = 1.0f / z;

    const float* Vb = g_Vh + (size_t)bh * N_ * D_;
    float acc0 = 0.f, acc1 = 0.f;
#pragma unroll 8
    for (int j = 0; j < 64; j++) {
        float p  = pw[w][j];
        int   kj = sk[w][j];
        acc0 += p * __ldg(Vb + (size_t)kj * D_ + lane);
        acc1 += p * __ldg(Vb + (size_t)kj * D_ + lane + 32);
    }

    int b = bh >> 4, h = bh & 15;
    size_t obase = ((size_t)(b * N_ + qr)) * HID_ + h * D_ + lane;
    g_ctx[obase]      = acc0 * invZ;
    g_ctx[obase + 32] = acc1 * invZ;
}

// ---------------------------------------------------------------------------
extern "C" void kernel_launch(void* const* d_in, const int* in_sizes, int n_in,
                              void* d_out, int out_size)
{
    const float* q    = (const float*)d_in[0];
    const float* k    = (const float*)d_in[1];
    const float* v    = (const float*)d_in[2];
    const float* wq_w = (const float*)d_in[5];
    const float* wq_b = (const float*)d_in[6];
    const float* wk_w = (const float*)d_in[7];
    const float* wk_b = (const float*)d_in[8];
    const float* wv_w = (const float*)d_in[9];
    const float* wv_b = (const float*)d_in[10];
    const float* wo_w = (const float*)d_in[11];
    const float* wo_b = (const float*)d_in[12];
    float* out = (float*)d_out;

    float *Qh, *Kh, *Vh, *ctx;
    __nv_bfloat16 *Vxhi, *Vxlo, *Whi, *Wlo, *Chi, *Clo;
    __nv_bfloat16 *Q3, *K3;
    cudaGetSymbolAddress((void**)&Qh,   g_Qh);
    cudaGetSymbolAddress((void**)&Kh,   g_Kh);
    cudaGetSymbolAddress((void**)&Vh,   g_Vh);
    cudaGetSymbolAddress((void**)&ctx,  g_ctx);
    cudaGetSymbolAddress((void**)&Vxhi, g_Vxhi);
    cudaGetSymbolAddress((void**)&Vxlo, g_Vxlo);
    cudaGetSymbolAddress((void**)&Whi,  g_Whi);
    cudaGetSymbolAddress((void**)&Wlo,  g_Wlo);
    cudaGetSymbolAddress((void**)&Chi,  g_Chi);
    cudaGetSymbolAddress((void**)&Clo,  g_Clo);
    cudaGetSymbolAddress((void**)&Q3,   g_Q3);
    cudaGetSymbolAddress((void**)&K3,   g_K3);

    const int NX4 = M_ * HID_ / 4;
    const int NW4 = HID_ * HID_ / 4;
    const int NH  = BH_ * N_ * D_;        // 4194304

    split_kernel<<<NX4/256, 256>>>(v,    Vxhi, Vxlo, NX4);
    split_kernel<<<NW4/256, 256>>>(wv_w, Whi,             Wlo,             NW4);
    split_kernel<<<NW4/256, 256>>>(wo_w, Whi + HID_*HID_, Wlo + HID_*HID_, NW4);

    // Q/K projections: fp32 exact (frozen)
    dim3 gQK(HID_ / 128, M_ / 128, 2);    // 8 x 32 x 2
    sgemm_qk<<<gQK, 256>>>(q, wq_w, wq_b, Qh, k, wk_w, wk_b, Kh);

    // V projection: tensor cores
    dim3 gProj(HID_ / 128, M_ / 128);     // 8 x 32
    hmma_gemm<<<gProj, 256>>>(Vxhi, Vxlo, Whi, Wlo, wv_b, Vh, 0);

    // 3-term splits of Qh / Kh
    split3_kernel<<<NH/256, 256>>>(Qh, Q3, Q3 + NH, Q3 + 2*NH, NH);
    split3_kernel<<<NH/256, 256>>>(Kh, K3, K3 + NH, K3 + 2*NH, NH);

    // scores: 6-pass split-3 bf16 HMMA
    dim3 gSc(N_ / 128, N_ / 128, BH_);    // 16 x 16 x 32
    scores_s3g<<<gSc, 256>>>();

    // exact top-64 + softmax + PV
    topk_pv_kernel<<<(B_ * N_ * H_) / 4, 128>>>();

    // O projection: tensor cores
    split_kernel<<<NX4/256, 256>>>(ctx, Chi, Clo, NX4);
    hmma_gemm<<<gProj, 256>>>(Chi, Clo, Whi + HID_*HID_, Wlo + HID_*HID_,
                              wo_b, out, 1);
}

// round 11
// speedup vs baseline: 1.3353x; 1.0005x over previous
#include <cuda_runtime.h>
#include <cuda_bf16.h>
#include <cstdint>
#include <cstddef>
#include <math.h>

#define B_   2
#define N_   2048
#define HID_ 1024
#define H_   16
#define D_   64
#define BH_  (B_*H_)     // 32
#define M_   (B_*N_)     // 4096
#define TOPK_ 64

// fp32 scratch
__device__ float g_Qh[BH_*N_*D_];             // [bh][n][d] (pre-scaled 0.125)
__device__ float g_Kh[BH_*N_*D_];
__device__ float g_Vh[BH_*N_*D_];
__device__ float g_S[134217728];              // 537 MB [bh][q][k]
__device__ float g_ctx[M_*HID_];

// 3-term splits of Qh / Kh for tensor-core scores (h/m/l each)
__device__ __nv_bfloat16 g_Q3[3][BH_*N_*D_];
__device__ __nv_bfloat16 g_K3[3][BH_*N_*D_];

// ---------------------------------------------------------------------------
#define LDSM_X4(r0,r1,r2,r3,addr) \
    asm volatile("ldmatrix.sync.aligned.m8n8.x4.shared.b16 {%0,%1,%2,%3}, [%4];" \
        : "=r"(r0), "=r"(r1), "=r"(r2), "=r"(r3) : "r"(addr))
#define LDSM_X2(r0,r1,addr) \
    asm volatile("ldmatrix.sync.aligned.m8n8.x2.shared.b16 {%0,%1}, [%2];" \
        : "=r"(r0), "=r"(r1) : "r"(addr))
#define MMA16816(c0,c1,c2,c3,a0,a1,a2,a3,b0,b1) \
    asm volatile("mma.sync.aligned.m16n8k16.row.col.f32.bf16.bf16.f32 " \
        "{%0,%1,%2,%3}, {%4,%5,%6,%7}, {%8,%9}, {%0,%1,%2,%3};" \
        : "+f"(c0), "+f"(c1), "+f"(c2), "+f"(c3) \
        : "r"(a0), "r"(a1), "r"(a2), "r"(a3), "r"(b0), "r"(b1))

__device__ __forceinline__ uint32_t smem_u32(const void* p) {
    uint32_t a;
    asm("{ .reg .u64 t; cvta.to.shared.u64 t, %1; cvt.u32.u64 %0, t; }"
        : "=r"(a) : "l"(p));
    return a;
}
__device__ __forceinline__ uint32_t bf2pack(__nv_bfloat16 a, __nv_bfloat16 b) {
    __nv_bfloat162 t; t.x = a; t.y = b;
    return *(uint32_t*)&t;
}

// ---------------------------------------------------------------------------
// fp32 SGEMM body (BIT-IDENTICAL math to R9 sgemm_qk; shared buf via pointer)
// ---------------------------------------------------------------------------
#define ASF(cur,kk,c) Asp[((cur)*8+(kk))*128+(c)]
#define BSF(cur,kk,c) Bsp[((cur)*8+(kk))*128+(c)]

__device__ __forceinline__ void sgemm_body(
    const float* __restrict__ X, const float* __restrict__ W,
    const float* __restrict__ bias, float* __restrict__ Out,
    float oscale, int n0, int o0, char* fbuf)
{
    const int K = HID_;
    float* Asp = (float*)fbuf;            // [2][8][128] = 8192 B
    float* Bsp = (float*)(fbuf + 8192);   // 8192 B
    int tid = threadIdx.x;

    int lrow = tid >> 1;
    int lkq  = (tid & 1) * 4;
    const float* Xp = X + (size_t)(n0 + lrow) * K + lkq;
    const float* Wp = W + (size_t)(o0 + lrow) * K + lkq;

    {
        float4 xa = *(const float4*)Xp;
        float4 wa = *(const float4*)Wp;
        ASF(0, lkq+0, lrow) = xa.x; ASF(0, lkq+1, lrow) = xa.y;
        ASF(0, lkq+2, lrow) = xa.z; ASF(0, lkq+3, lrow) = xa.w;
        BSF(0, lkq+0, lrow) = wa.x; BSF(0, lkq+1, lrow) = wa.y;
        BSF(0, lkq+2, lrow) = wa.z; BSF(0, lkq+3, lrow) = wa.w;
    }
    __syncthreads();

    int tx = tid & 15, ty = tid >> 4;
    float c[8][8];
#pragma unroll
    for (int i = 0; i < 8; i++)
#pragma unroll
        for (int j = 0; j < 8; j++) c[i][j] = 0.f;

    const int NSTEP = K / 8;
#pragma unroll 2
    for (int k0 = 0; k0 < NSTEP; k0++) {
        int cur = k0 & 1;
        float4 xn, wn;
        if (k0 < NSTEP - 1) {
            xn = *(const float4*)(Xp + (k0 + 1) * 8);
            wn = *(const float4*)(Wp + (k0 + 1) * 8);
        }
#pragma unroll
        for (int kk = 0; kk < 8; kk++) {
            float a[8], b[8];
            *(float4*)&a[0] = *(const float4*)&ASF(cur, kk, ty*8);
            *(float4*)&a[4] = *(const float4*)&ASF(cur, kk, ty*8+4);
            *(float4*)&b[0] = *(const float4*)&BSF(cur, kk, tx*8);
            *(float4*)&b[4] = *(const float4*)&BSF(cur, kk, tx*8+4);
#pragma unroll
            for (int i = 0; i < 8; i++)
#pragma unroll
                for (int j = 0; j < 8; j++)
                    c[i][j] += a[i] * b[j];
        }
        if (k0 < NSTEP - 1) {
            int nxt = cur ^ 1;
            ASF(nxt, lkq+0, lrow) = xn.x; ASF(nxt, lkq+1, lrow) = xn.y;
            ASF(nxt, lkq+2, lrow) = xn.z; ASF(nxt, lkq+3, lrow) = xn.w;
            BSF(nxt, lkq+0, lrow) = wn.x; BSF(nxt, lkq+1, lrow) = wn.y;
            BSF(nxt, lkq+2, lrow) = wn.z; BSF(nxt, lkq+3, lrow) = wn.w;
            __syncthreads();
        }
    }

    float bfr[8];
#pragma unroll
    for (int j = 0; j < 8; j++) bfr[j] = __ldg(bias + o0 + tx*8 + j);

#pragma unroll
    for (int i = 0; i < 8; i++) {
        int n = n0 + ty * 8 + i;
        int o = o0 + tx * 8;
        int b = n >> 11, nn = n & 2047;
        int h = o >> 6,  d  = o & 63;
        size_t idx = (((size_t)(b * H_ + h) * N_) + nn) * D_ + d;
        float4 v0, v1;
        v0.x = (c[i][0] + bfr[0]) * oscale;
        v0.y = (c[i][1] + bfr[1]) * oscale;
        v0.z = (c[i][2] + bfr[2]) * oscale;
        v0.w = (c[i][3] + bfr[3]) * oscale;
        v1.x = (c[i][4] + bfr[4]) * oscale;
        v1.y = (c[i][5] + bfr[5]) * oscale;
        v1.z = (c[i][6] + bfr[6]) * oscale;
        v1.w = (c[i][7] + bfr[7]) * oscale;
        *(float4*)(Out + idx)     = v0;
        *(float4*)(Out + idx + 4) = v1;
    }
}

// ---------------------------------------------------------------------------
// HMMA split-bf16 GEMM body with ON-THE-FLY fp32 -> hi/lo split.
// Same split formula and same MMA order as R9 hmma_gemm => bit-identical out.
// ---------------------------------------------------------------------------
#define TS_   5120          // tile size in bf16 entries (128 rows * 40)

__device__ __forceinline__ void hmma_f32_body(
    const float* __restrict__ Af, const float* __restrict__ Bf,
    const float* __restrict__ bias, float* __restrict__ Out,
    int mode, int n0, int o0, char* fbuf)
{
    __nv_bfloat16* smbuf = (__nv_bfloat16*)fbuf;   // 4 tiles, 40960 B
    int tid  = threadIdx.x;
    int wid  = tid >> 5, lane = tid & 31;
    int wm   = wid >> 2;
    int wn   = wid & 3;

    uint32_t smb = smem_u32(smbuf);

    float c[4][4][4];
#pragma unroll
    for (int mt = 0; mt < 4; mt++)
#pragma unroll
        for (int nt = 0; nt < 4; nt++)
#pragma unroll
            for (int r = 0; r < 4; r++) c[mt][nt][r] = 0.f;

    // transfer map: j in 0..3 -> (src A or B, half h). row = sub>>2, seg = sub&3
    int rowm[4], segm[4];
    const float* gbase[4];
#pragma unroll
    for (int j = 0; j < 4; j++) {
        int isB  = j >> 1;
        int sub  = ((j & 1) << 8) + tid;       // 0..511
        rowm[j] = sub >> 2; segm[j] = sub & 3;
        const float* base = isB ? Bf : Af;
        int grow = (isB ? o0 : n0) + rowm[j];
        gbase[j] = base + (size_t)grow * HID_ + segm[j] * 8;
    }
    uint32_t soffh[4], soffl[4];
#pragma unroll
    for (int j = 0; j < 4; j++) {
        int isB = j >> 1;
        uint32_t e = (uint32_t)(rowm[j] * 40 + segm[j] * 8);
        soffh[j] = (uint32_t)(((isB ? 2 : 0) * TS_ + e) * 2);
        soffl[j] = (uint32_t)(((isB ? 3 : 1) * TS_ + e) * 2);
    }

    uint32_t laneA = (uint32_t)((lane & 15) * 80 + (lane >> 4) * 16);
    uint32_t laneB = (uint32_t)((lane & 7) * 80 + ((lane >> 3) & 1) * 16);
    uint32_t aBase0 = smb + (uint32_t)(wm * 64 * 80) + laneA;
    uint32_t bBase0 = smb + (uint32_t)(wn * 32 * 80) + laneB;

    float4 pf0[4], pf1[4];
#pragma unroll
    for (int j = 0; j < 4; j++) {
        pf0[j] = *(const float4*)gbase[j];
        pf1[j] = *(const float4*)(gbase[j] + 4);
    }
#pragma unroll
    for (int j = 0; j < 4; j++) {
        float fv[8] = {pf0[j].x, pf0[j].y, pf0[j].z, pf0[j].w,
                       pf1[j].x, pf1[j].y, pf1[j].z, pf1[j].w};
        __nv_bfloat16 hh[8], ll[8];
#pragma unroll
        for (int e = 0; e < 8; e++) {
            hh[e] = __float2bfloat16_rn(fv[e]);
            ll[e] = __float2bfloat16_rn(fv[e] - __bfloat162float(hh[e]));
        }
        uint4 hv, lv;
        hv.x = bf2pack(hh[0], hh[1]); hv.y = bf2pack(hh[2], hh[3]);
        hv.z = bf2pack(hh[4], hh[5]); hv.w = bf2pack(hh[6], hh[7]);
        lv.x = bf2pack(ll[0], ll[1]); lv.y = bf2pack(ll[2], ll[3]);
        lv.z = bf2pack(ll[4], ll[5]); lv.w = bf2pack(ll[6], ll[7]);
        *(uint4*)((char*)smbuf + soffh[j]) = hv;
        *(uint4*)((char*)smbuf + soffl[j]) = lv;
    }
    __syncthreads();

    for (int kc = 0; kc < 32; kc++) {
        if (kc < 31) {
#pragma unroll
            for (int j = 0; j < 4; j++) {
                pf0[j] = *(const float4*)(gbase[j] + (kc + 1) * 32);
                pf1[j] = *(const float4*)(gbase[j] + (kc + 1) * 32 + 4);
            }
        }

#pragma unroll
        for (int pass = 0; pass < 3; pass++) {
            uint32_t aT = aBase0 + (uint32_t)(((pass == 2) ? TS_ : 0) * 2);
            uint32_t bT = bBase0 + (uint32_t)((((pass == 1) ? 3 : 2) * TS_) * 2);
#pragma unroll
            for (int k16 = 0; k16 < 2; k16++) {
                uint32_t a[4][4];
#pragma unroll
                for (int mt = 0; mt < 4; mt++)
                    LDSM_X4(a[mt][0], a[mt][1], a[mt][2], a[mt][3],
                            aT + (uint32_t)(mt * 1280 + k16 * 32));
                uint32_t bf[4][2];
#pragma unroll
                for (int nt = 0; nt < 4; nt++)
                    LDSM_X2(bf[nt][0], bf[nt][1],
                            bT + (uint32_t)(nt * 640 + k16 * 32));
#pragma unroll
                for (int mt = 0; mt < 4; mt++)
#pragma unroll
                    for (int nt = 0; nt < 4; nt++)
                        MMA16816(c[mt][nt][0], c[mt][nt][1], c[mt][nt][2], c[mt][nt][3],
                                 a[mt][0], a[mt][1], a[mt][2], a[mt][3],
                                 bf[nt][0], bf[nt][1]);
            }
        }

        if (kc < 31) {
            __syncthreads();
#pragma unroll
            for (int j = 0; j < 4; j++) {
                float fv[8] = {pf0[j].x, pf0[j].y, pf0[j].z, pf0[j].w,
                               pf1[j].x, pf1[j].y, pf1[j].z, pf1[j].w};
                __nv_bfloat16 hh[8], ll[8];
#pragma unroll
                for (int e = 0; e < 8; e++) {
                    hh[e] = __float2bfloat16_rn(fv[e]);
                    ll[e] = __float2bfloat16_rn(fv[e] - __bfloat162float(hh[e]));
                }
                uint4 hv, lv;
                hv.x = bf2pack(hh[0], hh[1]); hv.y = bf2pack(hh[2], hh[3]);
                hv.z = bf2pack(hh[4], hh[5]); hv.w = bf2pack(hh[6], hh[7]);
                lv.x = bf2pack(ll[0], ll[1]); lv.y = bf2pack(ll[2], ll[3]);
                lv.z = bf2pack(ll[4], ll[5]); lv.w = bf2pack(ll[6], ll[7]);
                *(uint4*)((char*)smbuf + soffh[j]) = hv;
                *(uint4*)((char*)smbuf + soffl[j]) = lv;
            }
            __syncthreads();
        }
    }

    int row_l = lane >> 2;
    int col_l = (lane & 3) * 2;
#pragma unroll
    for (int nt = 0; nt < 4; nt++) {
        int o = o0 + wn * 32 + nt * 8 + col_l;
        float bv0 = __ldg(bias + o);
        float bv1 = __ldg(bias + o + 1);
#pragma unroll
        for (int mt = 0; mt < 4; mt++) {
            int n = n0 + wm * 64 + mt * 16 + row_l;
#pragma unroll
            for (int half = 0; half < 2; half++) {
                int nn2 = n + half * 8;
                size_t idx;
                if (mode == 0) {
                    int b = nn2 >> 11, nr = nn2 & 2047;
                    int h = o >> 6,  d0 = o & 63;
                    idx = (((size_t)(b * H_ + h) * N_) + nr) * D_ + d0;
                } else {
                    idx = (size_t)nn2 * HID_ + o;
                }
                float2 vv;
                vv.x = c[mt][nt][half * 2 + 0] + bv0;
                vv.y = c[mt][nt][half * 2 + 1] + bv1;
                *(float2*)(Out + idx) = vv;
            }
        }
    }
}

// ---------------------------------------------------------------------------
// fused_front: 768 blocks. id%3 in {0,1} -> fp32 Q/K projection tile,
// id%3 == 2 -> V projection HMMA tile. Complementary pipes co-scheduled.
// ---------------------------------------------------------------------------
__global__ __launch_bounds__(256, 2) void fused_front(
    const float* __restrict__ q,  const float* __restrict__ wq_w,
    const float* __restrict__ wq_b, float* __restrict__ Qh,
    const float* __restrict__ k,  const float* __restrict__ wk_w,
    const float* __restrict__ wk_b, float* __restrict__ Kh,
    const float* __restrict__ v,  const float* __restrict__ wv_w,
    const float* __restrict__ wv_b, float* __restrict__ Vh)
{
    __shared__ __align__(16) char fbuf[40960];
    int id = blockIdx.x;
    int r  = id % 3;
    int g  = id / 3;

    if (r < 2) {
        int t   = g * 2 + r;          // 0..511
        int z   = t >> 8;             // 0 = Q, 1 = K
        int rem = t & 255;
        int o0  = (rem & 7) * 128;
        int n0  = (rem >> 3) * 128;
        if (z == 0)
            sgemm_body(q, wq_w, wq_b, Qh, 0.125f, n0, o0, fbuf);
        else
            sgemm_body(k, wk_w, wk_b, Kh, 1.0f,   n0, o0, fbuf);
    } else {
        int t  = g;                   // 0..255
        int o0 = (t & 7) * 128;
        int n0 = (t >> 3) * 128;
        hmma_f32_body(v, wv_w, wv_b, Vh, 0, n0, o0, fbuf);
    }
}

// O projection standalone (after topk)
__global__ __launch_bounds__(256, 2) void hmma_o(
    const float* __restrict__ ctx, const float* __restrict__ wo_w,
    const float* __restrict__ wo_b, float* __restrict__ Out)
{
    __shared__ __align__(16) char fbuf[40960];
    hmma_f32_body(ctx, wo_w, wo_b, Out, 1,
                  blockIdx.y * 128, blockIdx.x * 128, fbuf);
}

// ---------------------------------------------------------------------------
// Split fp32 -> bf16 h + m + l for BOTH Qh and Kh in one launch
// ---------------------------------------------------------------------------
__global__ __launch_bounds__(256) void split3_qk(int n)
{
    int i = blockIdx.x * 256 + threadIdx.x;
    const float* src;
    __nv_bfloat16 *h, *m, *l;
    int j;
    if (i < n) { src = g_Qh; h = g_Q3[0]; m = g_Q3[1]; l = g_Q3[2]; j = i; }
    else       { src = g_Kh; h = g_K3[0]; m = g_K3[1]; l = g_K3[2]; j = i - n; }
    float x = src[j];
    __nv_bfloat16 hh = __float2bfloat16_rn(x);
    float r1 = x - __bfloat162float(hh);
    __nv_bfloat16 mm = __float2bfloat16_rn(r1);
    float r2 = r1 - __bfloat162float(mm);
    __nv_bfloat16 ll = __float2bfloat16_rn(r2);
    h[j] = hh; m[j] = mm; l[j] = ll;
}

// ---------------------------------------------------------------------------
// Scores, 6 resident tiles in dynamic smem, BIT-IDENTICAL accumulation order
// to R9 scores_s3g: rnd{0,1} -> kc{0,1} -> pass list -> k16{0,1}.
// Tiles (128 rows x 64 cols bf16, row stride 144 B, conflict-free):
//   0:Qh 1:Qm 2:Ql 3:Kh 4:Km 5:Kl.  108 KB dynamic smem, 2 CTAs/SM.
// ---------------------------------------------------------------------------
#define STRB_ 144                 // row stride bytes
#define TSB_  (128 * STRB_)       // tile bytes = 18432

__global__ __launch_bounds__(256, 2) void scores_s3r(void)
{
    extern __shared__ __align__(16) char dsm[];
    int tid  = threadIdx.x;
    int wid  = tid >> 5, lane = tid & 31;
    int wm   = wid >> 2;
    int wn   = wid & 3;
    int bh   = blockIdx.z;
    int k0   = blockIdx.x * 128;
    int q0   = blockIdx.y * 128;

    uint32_t smb = smem_u32(dsm);

    const __nv_bfloat16* tsrc[6] = {
        g_Q3[0] + (size_t)bh * N_ * D_, g_Q3[1] + (size_t)bh * N_ * D_,
        g_Q3[2] + (size_t)bh * N_ * D_, g_K3[0] + (size_t)bh * N_ * D_,
        g_K3[1] + (size_t)bh * N_ * D_, g_K3[2] + (size_t)bh * N_ * D_ };

    // load all 6 tiles once
#pragma unroll
    for (int t = 0; t < 6; t++) {
        int r0 = (t < 3) ? q0 : k0;
#pragma unroll
        for (int it = 0; it < 4; it++) {
            int sub = it * 256 + tid;        // 0..1023
            int row = sub >> 3, seg = sub & 7;
            *(uint4*)(dsm + t * TSB_ + row * STRB_ + seg * 16) =
                *(const uint4*)(tsrc[t] + (size_t)(r0 + row) * D_ + seg * 8);
        }
    }
    __syncthreads();

    float c[4][4][4];
#pragma unroll
    for (int mt = 0; mt < 4; mt++)
#pragma unroll
        for (int nt = 0; nt < 4; nt++)
#pragma unroll
            for (int r = 0; r < 4; r++) c[mt][nt][r] = 0.f;

    uint32_t laneA = (uint32_t)((lane & 15) * STRB_ + (lane >> 4) * 16);
    uint32_t laneB = (uint32_t)((lane & 7) * STRB_ + ((lane >> 3) & 1) * 16);
    uint32_t aBase0 = smb + (uint32_t)(wm * 64 * STRB_) + laneA;
    uint32_t bBase0 = smb + (uint32_t)(wn * 32 * STRB_) + laneB;

    // identical order to R9: rnd -> kc -> pass -> k16
#pragma unroll
    for (int rnd = 0; rnd < 2; rnd++) {
#pragma unroll
        for (int kc = 0; kc < 2; kc++) {
            int npass = rnd ? 2 : 4;
            for (int p = 0; p < npass; p++) {
                int at, bt;
                if (rnd == 0) { at = p >> 1;           bt = 3 + (p & 1); }
                else          { at = (p == 0) ? 0 : 2; bt = (p == 0) ? 5 : 3; }
                uint32_t aT = aBase0 + (uint32_t)(at * TSB_);
                uint32_t bT = bBase0 + (uint32_t)(bt * TSB_);
#pragma unroll
                for (int k16 = 0; k16 < 2; k16++) {
                    uint32_t coloff = (uint32_t)(kc * 64 + k16 * 32);
                    uint32_t a[4][4];
#pragma unroll
                    for (int mt = 0; mt < 4; mt++)
                        LDSM_X4(a[mt][0], a[mt][1], a[mt][2], a[mt][3],
                                aT + (uint32_t)(mt * 16 * STRB_) + coloff);
                    uint32_t bf[4][2];
#pragma unroll
                    for (int nt = 0; nt < 4; nt++)
                        LDSM_X2(bf[nt][0], bf[nt][1],
                                bT + (uint32_t)(nt * 8 * STRB_) + coloff);
#pragma unroll
                    for (int mt = 0; mt < 4; mt++)
#pragma unroll
                        for (int nt = 0; nt < 4; nt++)
                            MMA16816(c[mt][nt][0], c[mt][nt][1], c[mt][nt][2], c[mt][nt][3],
                                     a[mt][0], a[mt][1], a[mt][2], a[mt][3],
                                     bf[nt][0], bf[nt][1]);
                }
            }
        }
    }

    int row_l = lane >> 2;
    int col_l = (lane & 3) * 2;
    float* Sb = g_S + (size_t)bh * N_ * N_;
#pragma unroll
    for (int nt = 0; nt < 4; nt++) {
        int o = k0 + wn * 32 + nt * 8 + col_l;
#pragma unroll
        for (int mt = 0; mt < 4; mt++) {
            int n = q0 + wm * 64 + mt * 16 + row_l;
#pragma unroll
            for (int half = 0; half < 2; half++) {
                int qq = n + half * 8;
                float2 vv;
                vv.x = c[mt][nt][half * 2 + 0];
                vv.y = c[mt][nt][half * 2 + 1];
                *(float2*)(Sb + (size_t)qq * N_ + o) = vv;
            }
        }
    }
}

// ---------------------------------------------------------------------------
// topk_v3 (verbatim R7/R9): exact top-64 + softmax + PV.
// ---------------------------------------------------------------------------
__device__ __forceinline__ unsigned fflip(float f) {
    unsigned u = __float_as_uint(f);
    return (u & 0x80000000u) ? ~u : (u | 0x80000000u);
}
__device__ __forceinline__ float funflip(unsigned u) {
    unsigned v = (u & 0x80000000u) ? (u & 0x7FFFFFFFu) : ~u;
    return __uint_as_float(v);
}

#define CAP_ 320

__global__ __launch_bounds__(128) void topk_pv_kernel(void)
{
    __shared__ float          rows[4][2048];
    __shared__ unsigned       candV[4][CAP_];
    __shared__ unsigned short candI[4][CAP_];
    __shared__ int   sk[4][64];
    __shared__ float sv[4][64];
    __shared__ float pw[4][64];
    __shared__ int   ek[4][64];

    int w    = threadIdx.x >> 5;
    int lane = threadIdx.x & 31;
    int gq   = blockIdx.x * 4 + w;
    int bh   = gq >> 11;
    int qr   = gq & 2047;
    unsigned ltmask = (1u << lane) - 1u;

    const float* Sb = g_S + ((size_t)bh * N_ + qr) * N_;

    unsigned m1 = 0u, m2 = 0u;
#pragma unroll
    for (int it = 0; it < 16; it++) {
        float4 f = ((const float4*)Sb)[it * 32 + lane];
        *(float4*)&rows[w][it * 128 + lane * 4] = f;
        unsigned uu[4] = {fflip(f.x), fflip(f.y), fflip(f.z), fflip(f.w)};
#pragma unroll
        for (int r = 0; r < 4; r++) {
            unsigned x = uu[r];
            if (x > m1) { m2 = m1; m1 = x; }
            else if (x > m2) { m2 = x; }
        }
    }
    unsigned T0 = __reduce_min_sync(0xffffffffu, m2);
    __syncwarp();

    int cnt = 0;
#pragma unroll
    for (int it = 0; it < 16; it++) {
        float4 f = *(const float4*)&rows[w][it * 128 + lane * 4];
        cnt += (fflip(f.x) >= T0) + (fflip(f.y) >= T0)
             + (fflip(f.z) >= T0) + (fflip(f.w) >= T0);
    }
    int off = cnt;
#pragma unroll
    for (int d = 1; d < 32; d <<= 1) {
        int t = __shfl_up_sync(0xffffffffu, off, d);
        if (lane >= d) off += t;
    }
    int nc = __shfl_sync(0xffffffffu, off, 31);
    off -= cnt;

    if (nc <= CAP_) {
        int o2 = off;
#pragma unroll
        for (int it = 0; it < 16; it++) {
            float4 f = *(const float4*)&rows[w][it * 128 + lane * 4];
            unsigned uu[4] = {fflip(f.x), fflip(f.y), fflip(f.z), fflip(f.w)};
#pragma unroll
            for (int r = 0; r < 4; r++) {
                if (uu[r] >= T0) {
                    candV[w][o2] = uu[r];
                    candI[w][o2] = (unsigned short)(it * 128 + lane * 4 + r);
                    o2++;
                }
            }
        }
    }
    __syncwarp();

    unsigned X = 0u;
    if (nc <= CAP_) {
        unsigned cu[CAP_/32];
        unsigned short ci[CAP_/32];
#pragma unroll
        for (int jj = 0; jj < CAP_/32; jj++) {
            int idx = lane + jj * 32;
            cu[jj] = (idx < nc) ? candV[w][idx] : 0u;
            ci[jj] = (idx < nc) ? candI[w][idx] : 0;
        }
        unsigned t = 0u;
        for (int bit = 31; bit >= 0; bit--) {
            unsigned tt = t | (1u << bit);
            int c = 0;
#pragma unroll
            for (int jj = 0; jj < CAP_/32; jj++) c += (cu[jj] >= tt);
            c = __reduce_add_sync(0xffffffffu, c);
            if (c >= TOPK_) {
                t = tt;
                if (c == TOPK_) break;
            }
        }
        X = t;

        int g1 = 0, g2 = 0;
#pragma unroll
        for (int jj = 0; jj < CAP_/32; jj++) {
            int idx = lane + jj * 32;
            bool valid = (idx < nc);
            unsigned x = cu[jj];
            bool gt = valid && (x > X), eq = valid && (x == X);
            unsigned mg = __ballot_sync(0xffffffffu, gt);
            unsigned me = __ballot_sync(0xffffffffu, eq);
            if (gt) {
                int p = g1 + __popc(mg & ltmask);
                sk[w][p] = ci[jj];
                sv[w][p] = funflip(x);
            }
            if (eq) {
                int p = g2 + __popc(me & ltmask);
                if (p < 64) ek[w][p] = ci[jj];
            }
            g1 += __popc(mg);
            g2 += __popc(me);
        }
        __syncwarp();
        if (lane == 0) {
            int need = TOPK_ - g1;
            int ec   = g2 > 64 ? 64 : g2;
            float xv = funflip(X);
            for (int s2 = 0; s2 < need; s2++) {
                int best = 0x7FFFFFFF, bi = 0;
                for (int e = 0; e < ec; e++) {
                    int v2 = ek[w][e];
                    if (v2 < best) { best = v2; bi = e; }
                }
                ek[w][bi] = 0x7FFFFFFF;
                sk[w][g1 + s2] = best;
                sv[w][g1 + s2] = xv;
            }
        }
    } else {
        unsigned t = 0u;
        for (int bit = 31; bit >= 0; bit--) {
            unsigned tt = t | (1u << bit);
            int c = 0;
            for (int it = 0; it < 16; it++) {
                float4 f = *(const float4*)&rows[w][it * 128 + lane * 4];
                c += (fflip(f.x) >= tt) + (fflip(f.y) >= tt)
                   + (fflip(f.z) >= tt) + (fflip(f.w) >= tt);
            }
            c = __reduce_add_sync(0xffffffffu, c);
            if (c >= TOPK_) {
                t = tt;
                if (c == TOPK_) break;
            }
        }
        X = t;
        int g1 = 0, g2 = 0;
        for (int it = 0; it < 16; it++) {
            float4 f = *(const float4*)&rows[w][it * 128 + lane * 4];
            unsigned uu[4] = {fflip(f.x), fflip(f.y), fflip(f.z), fflip(f.w)};
#pragma unroll
            for (int r = 0; r < 4; r++) {
                unsigned x = uu[r];
                int kix = it * 128 + lane * 4 + r;
                bool gt = (x > X), eq = (x == X);
                unsigned mg = __ballot_sync(0xffffffffu, gt);
                unsigned me = __ballot_sync(0xffffffffu, eq);
                if (gt) {
                    int p = g1 + __popc(mg & ltmask);
                    sk[w][p] = kix;
                    sv[w][p] = funflip(x);
                }
                if (eq) {
                    int p = g2 + __popc(me & ltmask);
                    if (p < 64) ek[w][p] = kix;
                }
                g1 += __popc(mg);
                g2 += __popc(me);
            }
        }
        __syncwarp();
        if (lane == 0) {
            int need = TOPK_ - g1;
            int ec   = g2 > 64 ? 64 : g2;
            float xv = funflip(X);
            for (int s2 = 0; s2 < need; s2++) {
                int best = 0x7FFFFFFF, bi = 0;
                for (int e = 0; e < ec; e++) {
                    int v2 = ek[w][e];
                    if (v2 < best) { best = v2; bi = e; }
                }
                ek[w][bi] = 0x7FFFFFFF;
                sk[w][g1 + s2] = best;
                sv[w][g1 + s2] = xv;
            }
        }
    }
    __syncwarp();

    float v0 = sv[w][lane];
    float v1 = sv[w][lane + 32];
    float mx = funflip(__reduce_max_sync(0xffffffffu,
                 (unsigned)max(fflip(v0), fflip(v1))));
    float p0 = expf(v0 - mx);
    float p1 = expf(v1 - mx);
    pw[w][lane]      = p0;
    pw[w][lane + 32] = p1;
    float z = p0 + p1;
#pragma unroll
    for (int offx = 16; offx > 0; offx >>= 1)
        z += __shfl_xor_sync(0xffffffffu, z, offx);
    float invZ = 1.0f / z;

    const float* Vb = g_Vh + (size_t)bh * N_ * D_;
    float acc0 = 0.f, acc1 = 0.f;
#pragma unroll 8
    for (int j = 0; j < 64; j++) {
        float p  = pw[w][j];
        int   kj = sk[w][j];
        acc0 += p * __ldg(Vb + (size_t)kj * D_ + lane);
        acc1 += p * __ldg(Vb + (size_t)kj * D_ + lane + 32);
    }

    int b = bh >> 4, h = bh & 15;
    size_t obase = ((size_t)(b * N_ + qr)) * HID_ + h * D_ + lane;
    g_ctx[obase]      = acc0 * invZ;
    g_ctx[obase + 32] = acc1 * invZ;
}

// ---------------------------------------------------------------------------
extern "C" void kernel_launch(void* const* d_in, const int* in_sizes, int n_in,
                              void* d_out, int out_size)
{
    const float* q    = (const float*)d_in[0];
    const float* k    = (const float*)d_in[1];
    const float* v    = (const float*)d_in[2];
    const float* wq_w = (const float*)d_in[5];
    const float* wq_b = (const float*)d_in[6];
    const float* wk_w = (const float*)d_in[7];
    const float* wk_b = (const float*)d_in[8];
    const float* wv_w = (const float*)d_in[9];
    const float* wv_b = (const float*)d_in[10];
    const float* wo_w = (const float*)d_in[11];
    const float* wo_b = (const float*)d_in[12];
    float* out = (float*)d_out;

    float *Qh, *Kh, *Vh, *ctx;
    cudaGetSymbolAddress((void**)&Qh,  g_Qh);
    cudaGetSymbolAddress((void**)&Kh,  g_Kh);
    cudaGetSymbolAddress((void**)&Vh,  g_Vh);
    cudaGetSymbolAddress((void**)&ctx, g_ctx);

    // idempotent; needed for 108 KB dynamic smem
    cudaFuncSetAttribute(scores_s3r,
                         cudaFuncAttributeMaxDynamicSharedMemorySize, 6 * TSB_);

    const int NH = BH_ * N_ * D_;         // 4194304

    // Q/K fp32 projections + V HMMA projection, co-scheduled
    fused_front<<<768, 256>>>(q, wq_w, wq_b, Qh,
                              k, wk_w, wk_b, Kh,
                              v, wv_w, wv_b, Vh);

    // 3-term splits of Qh and Kh (one launch)
    split3_qk<<<2 * NH / 256, 256>>>(NH);

    // scores: 6-pass split-3 bf16 HMMA, resident tiles
    dim3 gSc(N_ / 128, N_ / 128, BH_);    // 16 x 16 x 32
    scores_s3r<<<gSc, 256, 6 * TSB_>>>();

    // exact top-64 + softmax + PV
    topk_pv_kernel<<<(B_ * N_ * H_) / 4, 128>>>();

    // O projection (on-the-fly split HMMA)
    dim3 gO(HID_ / 128, M_ / 128);        // 8 x 32
    hmma_o<<<gO, 256>>>(ctx, wo_w, wo_b, out);
}

// round 12
// speedup vs baseline: 1.3502x; 1.0112x over previous
#include <cuda_runtime.h>
#include <cuda_bf16.h>
#include <cstdint>
#include <cstddef>
#include <math.h>

#define B_   2
#define N_   2048
#define HID_ 1024
#define H_   16
#define D_   64
#define BH_  (B_*H_)     // 32
#define M_   (B_*N_)     // 4096
#define TOPK_ 64

// fp32 scratch
__device__ float g_Qh[BH_*N_*D_];             // [bh][n][d] (pre-scaled 0.125)
__device__ float g_Kh[BH_*N_*D_];
__device__ float g_Vh[BH_*N_*D_];
__device__ unsigned g_S[134217728];           // 537 MB [bh][q][k]  FLIPPED fp32 bits
__device__ float g_ctx[M_*HID_];

// 3-term splits of Qh / Kh for tensor-core scores (h/m/l each)
__device__ __nv_bfloat16 g_Q3[3][BH_*N_*D_];
__device__ __nv_bfloat16 g_K3[3][BH_*N_*D_];

// ---------------------------------------------------------------------------
#define LDSM_X4(r0,r1,r2,r3,addr) \
    asm volatile("ldmatrix.sync.aligned.m8n8.x4.shared.b16 {%0,%1,%2,%3}, [%4];" \
        : "=r"(r0), "=r"(r1), "=r"(r2), "=r"(r3) : "r"(addr))
#define LDSM_X2(r0,r1,addr) \
    asm volatile("ldmatrix.sync.aligned.m8n8.x2.shared.b16 {%0,%1}, [%2];" \
        : "=r"(r0), "=r"(r1) : "r"(addr))
#define MMA16816(c0,c1,c2,c3,a0,a1,a2,a3,b0,b1) \
    asm volatile("mma.sync.aligned.m16n8k16.row.col.f32.bf16.bf16.f32 " \
        "{%0,%1,%2,%3}, {%4,%5,%6,%7}, {%8,%9}, {%0,%1,%2,%3};" \
        : "+f"(c0), "+f"(c1), "+f"(c2), "+f"(c3) \
        : "r"(a0), "r"(a1), "r"(a2), "r"(a3), "r"(b0), "r"(b1))

__device__ __forceinline__ uint32_t smem_u32(const void* p) {
    uint32_t a;
    asm("{ .reg .u64 t; cvta.to.shared.u64 t, %1; cvt.u32.u64 %0, t; }"
        : "=r"(a) : "l"(p));
    return a;
}
__device__ __forceinline__ uint32_t bf2pack(__nv_bfloat16 a, __nv_bfloat16 b) {
    __nv_bfloat162 t; t.x = a; t.y = b;
    return *(uint32_t*)&t;
}
__device__ __forceinline__ unsigned fflip(float f) {
    unsigned u = __float_as_uint(f);
    return (u & 0x80000000u) ? ~u : (u | 0x80000000u);
}
__device__ __forceinline__ float funflip(unsigned u) {
    unsigned v = (u & 0x80000000u) ? (u & 0x7FFFFFFFu) : ~u;
    return __uint_as_float(v);
}

// ---------------------------------------------------------------------------
// fp32 SGEMM body (BIT-IDENTICAL math; shared buf via pointer)
// ---------------------------------------------------------------------------
#define ASF(cur,kk,c) Asp[((cur)*8+(kk))*128+(c)]
#define BSF(cur,kk,c) Bsp[((cur)*8+(kk))*128+(c)]

__device__ __forceinline__ void sgemm_body(
    const float* __restrict__ X, const float* __restrict__ W,
    const float* __restrict__ bias, float* __restrict__ Out,
    float oscale, int n0, int o0, char* fbuf)
{
    const int K = HID_;
    float* Asp = (float*)fbuf;            // [2][8][128] = 8192 B
    float* Bsp = (float*)(fbuf + 8192);   // 8192 B
    int tid = threadIdx.x;

    int lrow = tid >> 1;
    int lkq  = (tid & 1) * 4;
    const float* Xp = X + (size_t)(n0 + lrow) * K + lkq;
    const float* Wp = W + (size_t)(o0 + lrow) * K + lkq;

    {
        float4 xa = *(const float4*)Xp;
        float4 wa = *(const float4*)Wp;
        ASF(0, lkq+0, lrow) = xa.x; ASF(0, lkq+1, lrow) = xa.y;
        ASF(0, lkq+2, lrow) = xa.z; ASF(0, lkq+3, lrow) = xa.w;
        BSF(0, lkq+0, lrow) = wa.x; BSF(0, lkq+1, lrow) = wa.y;
        BSF(0, lkq+2, lrow) = wa.z; BSF(0, lkq+3, lrow) = wa.w;
    }
    __syncthreads();

    int tx = tid & 15, ty = tid >> 4;
    float c[8][8];
#pragma unroll
    for (int i = 0; i < 8; i++)
#pragma unroll
        for (int j = 0; j < 8; j++) c[i][j] = 0.f;

    const int NSTEP = K / 8;
#pragma unroll 2
    for (int k0 = 0; k0 < NSTEP; k0++) {
        int cur = k0 & 1;
        float4 xn, wn;
        if (k0 < NSTEP - 1) {
            xn = *(const float4*)(Xp + (k0 + 1) * 8);
            wn = *(const float4*)(Wp + (k0 + 1) * 8);
        }
#pragma unroll
        for (int kk = 0; kk < 8; kk++) {
            float a[8], b[8];
            *(float4*)&a[0] = *(const float4*)&ASF(cur, kk, ty*8);
            *(float4*)&a[4] = *(const float4*)&ASF(cur, kk, ty*8+4);
            *(float4*)&b[0] = *(const float4*)&BSF(cur, kk, tx*8);
            *(float4*)&b[4] = *(const float4*)&BSF(cur, kk, tx*8+4);
#pragma unroll
            for (int i = 0; i < 8; i++)
#pragma unroll
                for (int j = 0; j < 8; j++)
                    c[i][j] += a[i] * b[j];
        }
        if (k0 < NSTEP - 1) {
            int nxt = cur ^ 1;
            ASF(nxt, lkq+0, lrow) = xn.x; ASF(nxt, lkq+1, lrow) = xn.y;
            ASF(nxt, lkq+2, lrow) = xn.z; ASF(nxt, lkq+3, lrow) = xn.w;
            BSF(nxt, lkq+0, lrow) = wn.x; BSF(nxt, lkq+1, lrow) = wn.y;
            BSF(nxt, lkq+2, lrow) = wn.z; BSF(nxt, lkq+3, lrow) = wn.w;
            __syncthreads();
        }
    }

    float bfr[8];
#pragma unroll
    for (int j = 0; j < 8; j++) bfr[j] = __ldg(bias + o0 + tx*8 + j);

#pragma unroll
    for (int i = 0; i < 8; i++) {
        int n = n0 + ty * 8 + i;
        int o = o0 + tx * 8;
        int b = n >> 11, nn = n & 2047;
        int h = o >> 6,  d  = o & 63;
        size_t idx = (((size_t)(b * H_ + h) * N_) + nn) * D_ + d;
        float4 v0, v1;
        v0.x = (c[i][0] + bfr[0]) * oscale;
        v0.y = (c[i][1] + bfr[1]) * oscale;
        v0.z = (c[i][2] + bfr[2]) * oscale;
        v0.w = (c[i][3] + bfr[3]) * oscale;
        v1.x = (c[i][4] + bfr[4]) * oscale;
        v1.y = (c[i][5] + bfr[5]) * oscale;
        v1.z = (c[i][6] + bfr[6]) * oscale;
        v1.w = (c[i][7] + bfr[7]) * oscale;
        *(float4*)(Out + idx)     = v0;
        *(float4*)(Out + idx + 4) = v1;
    }
}

// ---------------------------------------------------------------------------
// HMMA split-bf16 GEMM body with ON-THE-FLY fp32 -> hi/lo split (verbatim R10)
// ---------------------------------------------------------------------------
#define TS_   5120          // tile size in bf16 entries (128 rows * 40)

__device__ __forceinline__ void hmma_f32_body(
    const float* __restrict__ Af, const float* __restrict__ Bf,
    const float* __restrict__ bias, float* __restrict__ Out,
    int mode, int n0, int o0, char* fbuf)
{
    __nv_bfloat16* smbuf = (__nv_bfloat16*)fbuf;   // 4 tiles, 40960 B
    int tid  = threadIdx.x;
    int wid  = tid >> 5, lane = tid & 31;
    int wm   = wid >> 2;
    int wn   = wid & 3;

    uint32_t smb = smem_u32(smbuf);

    float c[4][4][4];
#pragma unroll
    for (int mt = 0; mt < 4; mt++)
#pragma unroll
        for (int nt = 0; nt < 4; nt++)
#pragma unroll
            for (int r = 0; r < 4; r++) c[mt][nt][r] = 0.f;

    int rowm[4], segm[4];
    const float* gbase[4];
#pragma unroll
    for (int j = 0; j < 4; j++) {
        int isB  = j >> 1;
        int sub  = ((j & 1) << 8) + tid;       // 0..511
        rowm[j] = sub >> 2; segm[j] = sub & 3;
        const float* base = isB ? Bf : Af;
        int grow = (isB ? o0 : n0) + rowm[j];
        gbase[j] = base + (size_t)grow * HID_ + segm[j] * 8;
    }
    uint32_t soffh[4], soffl[4];
#pragma unroll
    for (int j = 0; j < 4; j++) {
        int isB = j >> 1;
        uint32_t e = (uint32_t)(rowm[j] * 40 + segm[j] * 8);
        soffh[j] = (uint32_t)(((isB ? 2 : 0) * TS_ + e) * 2);
        soffl[j] = (uint32_t)(((isB ? 3 : 1) * TS_ + e) * 2);
    }

    uint32_t laneA = (uint32_t)((lane & 15) * 80 + (lane >> 4) * 16);
    uint32_t laneB = (uint32_t)((lane & 7) * 80 + ((lane >> 3) & 1) * 16);
    uint32_t aBase0 = smb + (uint32_t)(wm * 64 * 80) + laneA;
    uint32_t bBase0 = smb + (uint32_t)(wn * 32 * 80) + laneB;

    float4 pf0[4], pf1[4];
#pragma unroll
    for (int j = 0; j < 4; j++) {
        pf0[j] = *(const float4*)gbase[j];
        pf1[j] = *(const float4*)(gbase[j] + 4);
    }
#pragma unroll
    for (int j = 0; j < 4; j++) {
        float fv[8] = {pf0[j].x, pf0[j].y, pf0[j].z, pf0[j].w,
                       pf1[j].x, pf1[j].y, pf1[j].z, pf1[j].w};
        __nv_bfloat16 hh[8], ll[8];
#pragma unroll
        for (int e = 0; e < 8; e++) {
            hh[e] = __float2bfloat16_rn(fv[e]);
            ll[e] = __float2bfloat16_rn(fv[e] - __bfloat162float(hh[e]));
        }
        uint4 hv, lv;
        hv.x = bf2pack(hh[0], hh[1]); hv.y = bf2pack(hh[2], hh[3]);
        hv.z = bf2pack(hh[4], hh[5]); hv.w = bf2pack(hh[6], hh[7]);
        lv.x = bf2pack(ll[0], ll[1]); lv.y = bf2pack(ll[2], ll[3]);
        lv.z = bf2pack(ll[4], ll[5]); lv.w = bf2pack(ll[6], ll[7]);
        *(uint4*)((char*)smbuf + soffh[j]) = hv;
        *(uint4*)((char*)smbuf + soffl[j]) = lv;
    }
    __syncthreads();

    for (int kc = 0; kc < 32; kc++) {
        if (kc < 31) {
#pragma unroll
            for (int j = 0; j < 4; j++) {
                pf0[j] = *(const float4*)(gbase[j] + (kc + 1) * 32);
                pf1[j] = *(const float4*)(gbase[j] + (kc + 1) * 32 + 4);
            }
        }

#pragma unroll
        for (int pass = 0; pass < 3; pass++) {
            uint32_t aT = aBase0 + (uint32_t)(((pass == 2) ? TS_ : 0) * 2);
            uint32_t bT = bBase0 + (uint32_t)((((pass == 1) ? 3 : 2) * TS_) * 2);
#pragma unroll
            for (int k16 = 0; k16 < 2; k16++) {
                uint32_t a[4][4];
#pragma unroll
                for (int mt = 0; mt < 4; mt++)
                    LDSM_X4(a[mt][0], a[mt][1], a[mt][2], a[mt][3],
                            aT + (uint32_t)(mt * 1280 + k16 * 32));
                uint32_t bf[4][2];
#pragma unroll
                for (int nt = 0; nt < 4; nt++)
                    LDSM_X2(bf[nt][0], bf[nt][1],
                            bT + (uint32_t)(nt * 640 + k16 * 32));
#pragma unroll
                for (int mt = 0; mt < 4; mt++)
#pragma unroll
                    for (int nt = 0; nt < 4; nt++)
                        MMA16816(c[mt][nt][0], c[mt][nt][1], c[mt][nt][2], c[mt][nt][3],
                                 a[mt][0], a[mt][1], a[mt][2], a[mt][3],
                                 bf[nt][0], bf[nt][1]);
            }
        }

        if (kc < 31) {
            __syncthreads();
#pragma unroll
            for (int j = 0; j < 4; j++) {
                float fv[8] = {pf0[j].x, pf0[j].y, pf0[j].z, pf0[j].w,
                               pf1[j].x, pf1[j].y, pf1[j].z, pf1[j].w};
                __nv_bfloat16 hh[8], ll[8];
#pragma unroll
                for (int e = 0; e < 8; e++) {
                    hh[e] = __float2bfloat16_rn(fv[e]);
                    ll[e] = __float2bfloat16_rn(fv[e] - __bfloat162float(hh[e]));
                }
                uint4 hv, lv;
                hv.x = bf2pack(hh[0], hh[1]); hv.y = bf2pack(hh[2], hh[3]);
                hv.z = bf2pack(hh[4], hh[5]); hv.w = bf2pack(hh[6], hh[7]);
                lv.x = bf2pack(ll[0], ll[1]); lv.y = bf2pack(ll[2], ll[3]);
                lv.z = bf2pack(ll[4], ll[5]); lv.w = bf2pack(ll[6], ll[7]);
                *(uint4*)((char*)smbuf + soffh[j]) = hv;
                *(uint4*)((char*)smbuf + soffl[j]) = lv;
            }
            __syncthreads();
        }
    }

    int row_l = lane >> 2;
    int col_l = (lane & 3) * 2;
#pragma unroll
    for (int nt = 0; nt < 4; nt++) {
        int o = o0 + wn * 32 + nt * 8 + col_l;
        float bv0 = __ldg(bias + o);
        float bv1 = __ldg(bias + o + 1);
#pragma unroll
        for (int mt = 0; mt < 4; mt++) {
            int n = n0 + wm * 64 + mt * 16 + row_l;
#pragma unroll
            for (int half = 0; half < 2; half++) {
                int nn2 = n + half * 8;
                size_t idx;
                if (mode == 0) {
                    int b = nn2 >> 11, nr = nn2 & 2047;
                    int h = o >> 6,  d0 = o & 63;
                    idx = (((size_t)(b * H_ + h) * N_) + nr) * D_ + d0;
                } else {
                    idx = (size_t)nn2 * HID_ + o;
                }
                float2 vv;
                vv.x = c[mt][nt][half * 2 + 0] + bv0;
                vv.y = c[mt][nt][half * 2 + 1] + bv1;
                *(float2*)(Out + idx) = vv;
            }
        }
    }
}

// ---------------------------------------------------------------------------
// fused_front (verbatim R10)
// ---------------------------------------------------------------------------
__global__ __launch_bounds__(256, 2) void fused_front(
    const float* __restrict__ q,  const float* __restrict__ wq_w,
    const float* __restrict__ wq_b, float* __restrict__ Qh,
    const float* __restrict__ k,  const float* __restrict__ wk_w,
    const float* __restrict__ wk_b, float* __restrict__ Kh,
    const float* __restrict__ v,  const float* __restrict__ wv_w,
    const float* __restrict__ wv_b, float* __restrict__ Vh)
{
    __shared__ __align__(16) char fbuf[40960];
    int id = blockIdx.x;
    int r  = id % 3;
    int g  = id / 3;

    if (r < 2) {
        int t   = g * 2 + r;          // 0..511
        int z   = t >> 8;             // 0 = Q, 1 = K
        int rem = t & 255;
        int o0  = (rem & 7) * 128;
        int n0  = (rem >> 3) * 128;
        if (z == 0)
            sgemm_body(q, wq_w, wq_b, Qh, 0.125f, n0, o0, fbuf);
        else
            sgemm_body(k, wk_w, wk_b, Kh, 1.0f,   n0, o0, fbuf);
    } else {
        int t  = g;                   // 0..255
        int o0 = (t & 7) * 128;
        int n0 = (t >> 3) * 128;
        hmma_f32_body(v, wv_w, wv_b, Vh, 0, n0, o0, fbuf);
    }
}

// O projection standalone (after topk)
__global__ __launch_bounds__(256, 2) void hmma_o(
    const float* __restrict__ ctx, const float* __restrict__ wo_w,
    const float* __restrict__ wo_b, float* __restrict__ Out)
{
    __shared__ __align__(16) char fbuf[40960];
    hmma_f32_body(ctx, wo_w, wo_b, Out, 1,
                  blockIdx.y * 128, blockIdx.x * 128, fbuf);
}

// ---------------------------------------------------------------------------
// Split fp32 -> bf16 h + m + l for BOTH Qh and Kh in one launch (verbatim R10)
// ---------------------------------------------------------------------------
__global__ __launch_bounds__(256) void split3_qk(int n)
{
    int i = blockIdx.x * 256 + threadIdx.x;
    const float* src;
    __nv_bfloat16 *h, *m, *l;
    int j;
    if (i < n) { src = g_Qh; h = g_Q3[0]; m = g_Q3[1]; l = g_Q3[2]; j = i; }
    else       { src = g_Kh; h = g_K3[0]; m = g_K3[1]; l = g_K3[2]; j = i - n; }
    float x = src[j];
    __nv_bfloat16 hh = __float2bfloat16_rn(x);
    float r1 = x - __bfloat162float(hh);
    __nv_bfloat16 mm = __float2bfloat16_rn(r1);
    float r2 = r1 - __bfloat162float(mm);
    __nv_bfloat16 ll = __float2bfloat16_rn(r2);
    h[j] = hh; m[j] = mm; l[j] = ll;
}

// ---------------------------------------------------------------------------
// Scores (resident tiles, verbatim R10 math) -- epilogue stores FLIPPED bits.
// fflip is a monotone bijection; topk ordering identical, funflip exact.
// ---------------------------------------------------------------------------
#define STRB_ 144                 // row stride bytes
#define TSB_  (128 * STRB_)       // tile bytes = 18432

__global__ __launch_bounds__(256, 2) void scores_s3r(void)
{
    extern __shared__ __align__(16) char dsm[];
    int tid  = threadIdx.x;
    int wid  = tid >> 5, lane = tid & 31;
    int wm   = wid >> 2;
    int wn   = wid & 3;
    int bh   = blockIdx.z;
    int k0   = blockIdx.x * 128;
    int q0   = blockIdx.y * 128;

    uint32_t smb = smem_u32(dsm);

    const __nv_bfloat16* tsrc[6] = {
        g_Q3[0] + (size_t)bh * N_ * D_, g_Q3[1] + (size_t)bh * N_ * D_,
        g_Q3[2] + (size_t)bh * N_ * D_, g_K3[0] + (size_t)bh * N_ * D_,
        g_K3[1] + (size_t)bh * N_ * D_, g_K3[2] + (size_t)bh * N_ * D_ };

#pragma unroll
    for (int t = 0; t < 6; t++) {
        int r0 = (t < 3) ? q0 : k0;
#pragma unroll
        for (int it = 0; it < 4; it++) {
            int sub = it * 256 + tid;
            int row = sub >> 3, seg = sub & 7;
            *(uint4*)(dsm + t * TSB_ + row * STRB_ + seg * 16) =
                *(const uint4*)(tsrc[t] + (size_t)(r0 + row) * D_ + seg * 8);
        }
    }
    __syncthreads();

    float c[4][4][4];
#pragma unroll
    for (int mt = 0; mt < 4; mt++)
#pragma unroll
        for (int nt = 0; nt < 4; nt++)
#pragma unroll
            for (int r = 0; r < 4; r++) c[mt][nt][r] = 0.f;

    uint32_t laneA = (uint32_t)((lane & 15) * STRB_ + (lane >> 4) * 16);
    uint32_t laneB = (uint32_t)((lane & 7) * STRB_ + ((lane >> 3) & 1) * 16);
    uint32_t aBase0 = smb + (uint32_t)(wm * 64 * STRB_) + laneA;
    uint32_t bBase0 = smb + (uint32_t)(wn * 32 * STRB_) + laneB;

#pragma unroll
    for (int rnd = 0; rnd < 2; rnd++) {
#pragma unroll
        for (int kc = 0; kc < 2; kc++) {
            int npass = rnd ? 2 : 4;
            for (int p = 0; p < npass; p++) {
                int at, bt;
                if (rnd == 0) { at = p >> 1;           bt = 3 + (p & 1); }
                else          { at = (p == 0) ? 0 : 2; bt = (p == 0) ? 5 : 3; }
                uint32_t aT = aBase0 + (uint32_t)(at * TSB_);
                uint32_t bT = bBase0 + (uint32_t)(bt * TSB_);
#pragma unroll
                for (int k16 = 0; k16 < 2; k16++) {
                    uint32_t coloff = (uint32_t)(kc * 64 + k16 * 32);
                    uint32_t a[4][4];
#pragma unroll
                    for (int mt = 0; mt < 4; mt++)
                        LDSM_X4(a[mt][0], a[mt][1], a[mt][2], a[mt][3],
                                aT + (uint32_t)(mt * 16 * STRB_) + coloff);
                    uint32_t bf[4][2];
#pragma unroll
                    for (int nt = 0; nt < 4; nt++)
                        LDSM_X2(bf[nt][0], bf[nt][1],
                                bT + (uint32_t)(nt * 8 * STRB_) + coloff);
#pragma unroll
                    for (int mt = 0; mt < 4; mt++)
#pragma unroll
                        for (int nt = 0; nt < 4; nt++)
                            MMA16816(c[mt][nt][0], c[mt][nt][1], c[mt][nt][2], c[mt][nt][3],
                                     a[mt][0], a[mt][1], a[mt][2], a[mt][3],
                                     bf[nt][0], bf[nt][1]);
                }
            }
        }
    }

    int row_l = lane >> 2;
    int col_l = (lane & 3) * 2;
    unsigned* Sb = g_S + (size_t)bh * N_ * N_;
#pragma unroll
    for (int nt = 0; nt < 4; nt++) {
        int o = k0 + wn * 32 + nt * 8 + col_l;
#pragma unroll
        for (int mt = 0; mt < 4; mt++) {
            int n = q0 + wm * 64 + mt * 16 + row_l;
#pragma unroll
            for (int half = 0; half < 2; half++) {
                int qq = n + half * 8;
                uint2 vv;
                vv.x = fflip(c[mt][nt][half * 2 + 0]);
                vv.y = fflip(c[mt][nt][half * 2 + 1]);
                *(uint2*)(Sb + (size_t)qq * N_ + o) = vv;
            }
        }
    }
}

// ---------------------------------------------------------------------------
// topk_v4: register-resident flipped row; scan compaction; early-exit greedy.
// Selection semantics & output bits identical to R10.
// ---------------------------------------------------------------------------
#define CAP_ 320

__global__ __launch_bounds__(128) void topk_pv_kernel(void)
{
    __shared__ unsigned       candV[4][CAP_];
    __shared__ unsigned short candI[4][CAP_];
    __shared__ int   sk[4][64];
    __shared__ float sv[4][64];
    __shared__ float pw[4][64];
    __shared__ int   ek[4][64];

    int w    = threadIdx.x >> 5;
    int lane = threadIdx.x & 31;
    int gq   = blockIdx.x * 4 + w;
    int bh   = gq >> 11;
    int qr   = gq & 2047;
    unsigned ltmask = (1u << lane) - 1u;

    const unsigned* Sb = g_S + ((size_t)bh * N_ + qr) * N_;

    // load 2048 flipped scores into 64 regs; track per-lane top-2
    unsigned u[64];
    unsigned m1 = 0u, m2 = 0u;
#pragma unroll
    for (int it = 0; it < 16; it++) {
        uint4 f = ((const uint4*)Sb)[it * 32 + lane];
        u[it*4+0] = f.x; u[it*4+1] = f.y; u[it*4+2] = f.z; u[it*4+3] = f.w;
#pragma unroll
        for (int r = 0; r < 4; r++) {
            unsigned x = u[it*4+r];
            if (x > m1) { m2 = m1; m1 = x; }
            else if (x > m2) { m2 = x; }
        }
    }
    unsigned T0 = __reduce_min_sync(0xffffffffu, m2);   // >=64 values >= T0

    // per-lane candidate count + exclusive scan
    int cnt = 0;
#pragma unroll
    for (int i = 0; i < 64; i++) cnt += (u[i] >= T0);
    int off = cnt;
#pragma unroll
    for (int d = 1; d < 32; d <<= 1) {
        int t = __shfl_up_sync(0xffffffffu, off, d);
        if (lane >= d) off += t;
    }
    int nc = __shfl_sync(0xffffffffu, off, 31);
    off -= cnt;

    // compact candidates (lane-major order, identical to R10)
    if (nc <= CAP_) {
        int o2 = off;
#pragma unroll
        for (int i = 0; i < 64; i++) {
            if (u[i] >= T0) {
                candV[w][o2] = u[i];
                candI[w][o2] = (unsigned short)((i >> 2) * 128 + lane * 4 + (i & 3));
                o2++;
            }
        }
    }
    __syncwarp();

    unsigned X = 0u;
    if (nc <= CAP_) {
        unsigned cu[CAP_/32];
        unsigned short ci[CAP_/32];
#pragma unroll
        for (int jj = 0; jj < CAP_/32; jj++) {
            int idx = lane + jj * 32;
            cu[jj] = (idx < nc) ? candV[w][idx] : 0u;
            ci[jj] = (idx < nc) ? candI[w][idx] : 0;
        }
        unsigned t = 0u;
        for (int bit = 31; bit >= 0; bit--) {
            unsigned tt = t | (1u << bit);
            int c = 0;
#pragma unroll
            for (int jj = 0; jj < CAP_/32; jj++) c += (cu[jj] >= tt);
            c = __reduce_add_sync(0xffffffffu, c);
            if (c >= TOPK_) {
                t = tt;
                if (c == TOPK_) break;
            }
        }
        X = t;

        int g1 = 0, g2 = 0;
#pragma unroll
        for (int jj = 0; jj < CAP_/32; jj++) {
            int idx = lane + jj * 32;
            bool valid = (idx < nc);
            unsigned x = cu[jj];
            bool gt = valid && (x > X), eq = valid && (x == X);
            unsigned mg = __ballot_sync(0xffffffffu, gt);
            unsigned me = __ballot_sync(0xffffffffu, eq);
            if (gt) {
                int p = g1 + __popc(mg & ltmask);
                sk[w][p] = ci[jj];
                sv[w][p] = funflip(x);
            }
            if (eq) {
                int p = g2 + __popc(me & ltmask);
                if (p < 64) ek[w][p] = ci[jj];
            }
            g1 += __popc(mg);
            g2 += __popc(me);
        }
        __syncwarp();
        if (lane == 0) {
            int need = TOPK_ - g1;
            int ec   = g2 > 64 ? 64 : g2;
            float xv = funflip(X);
            for (int s2 = 0; s2 < need; s2++) {
                int best = 0x7FFFFFFF, bi = 0;
                for (int e = 0; e < ec; e++) {
                    int v2 = ek[w][e];
                    if (v2 < best) { best = v2; bi = e; }
                }
                ek[w][bi] = 0x7FFFFFFF;
                sk[w][g1 + s2] = best;
                sv[w][g1 + s2] = xv;
            }
        }
    } else {
        // slow fallback from regs (prob ~0); same per-element ballot order
        unsigned t = 0u;
        for (int bit = 31; bit >= 0; bit--) {
            unsigned tt = t | (1u << bit);
            int c = 0;
#pragma unroll
            for (int i = 0; i < 64; i++) c += (u[i] >= tt);
            c = __reduce_add_sync(0xffffffffu, c);
            if (c >= TOPK_) {
                t = tt;
                if (c == TOPK_) break;
            }
        }
        X = t;
        int g1 = 0, g2 = 0;
        for (int i = 0; i < 64; i++) {
            unsigned x = u[i];
            int kix = (i >> 2) * 128 + lane * 4 + (i & 3);
            bool gt = (x > X), eq = (x == X);
            unsigned mg = __ballot_sync(0xffffffffu, gt);
            unsigned me = __ballot_sync(0xffffffffu, eq);
            if (gt) {
                int p = g1 + __popc(mg & ltmask);
                sk[w][p] = kix;
                sv[w][p] = funflip(x);
            }
            if (eq) {
                int p = g2 + __popc(me & ltmask);
                if (p < 64) ek[w][p] = kix;
            }
            g1 += __popc(mg);
            g2 += __popc(me);
        }
        __syncwarp();
        if (lane == 0) {
            int need = TOPK_ - g1;
            int ec   = g2 > 64 ? 64 : g2;
            float xv = funflip(X);
            for (int s2 = 0; s2 < need; s2++) {
                int best = 0x7FFFFFFF, bi = 0;
                for (int e = 0; e < ec; e++) {
                    int v2 = ek[w][e];
                    if (v2 < best) { best = v2; bi = e; }
                }
                ek[w][bi] = 0x7FFFFFFF;
                sk[w][g1 + s2] = best;
                sv[w][g1 + s2] = xv;
            }
        }
    }
    __syncwarp();

    // softmax over selected 64
    float v0 = sv[w][lane];
    float v1 = sv[w][lane + 32];
    float mx = funflip(__reduce_max_sync(0xffffffffu,
                 (unsigned)max(fflip(v0), fflip(v1))));
    float p0 = expf(v0 - mx);
    float p1 = expf(v1 - mx);
    pw[w][lane]      = p0;
    pw[w][lane + 32] = p1;
    float z = p0 + p1;
#pragma unroll
    for (int offx = 16; offx > 0; offx >>= 1)
        z += __shfl_xor_sync(0xffffffffu, z, offx);
    float invZ = 1.0f / z;

    // PV
    const float* Vb = g_Vh + (size_t)bh * N_ * D_;
    float acc0 = 0.f, acc1 = 0.f;
#pragma unroll 8
    for (int j = 0; j < 64; j++) {
        float p  = pw[w][j];
        int   kj = sk[w][j];
        acc0 += p * __ldg(Vb + (size_t)kj * D_ + lane);
        acc1 += p * __ldg(Vb + (size_t)kj * D_ + lane + 32);
    }

    int b = bh >> 4, h = bh & 15;
    size_t obase = ((size_t)(b * N_ + qr)) * HID_ + h * D_ + lane;
    g_ctx[obase]      = acc0 * invZ;
    g_ctx[obase + 32] = acc1 * invZ;
}

// ---------------------------------------------------------------------------
extern "C" void kernel_launch(void* const* d_in, const int* in_sizes, int n_in,
                              void* d_out, int out_size)
{
    const float* q    = (const float*)d_in[0];
    const float* k    = (const float*)d_in[1];
    const float* v    = (const float*)d_in[2];
    const float* wq_w = (const float*)d_in[5];
    const float* wq_b = (const float*)d_in[6];
    const float* wk_w = (const float*)d_in[7];
    const float* wk_b = (const float*)d_in[8];
    const float* wv_w = (const float*)d_in[9];
    const float* wv_b = (const float*)d_in[10];
    const float* wo_w = (const float*)d_in[11];
    const float* wo_b = (const float*)d_in[12];
    float* out = (float*)d_out;

    float *Qh, *Kh, *Vh, *ctx;
    cudaGetSymbolAddress((void**)&Qh,  g_Qh);
    cudaGetSymbolAddress((void**)&Kh,  g_Kh);
    cudaGetSymbolAddress((void**)&Vh,  g_Vh);
    cudaGetSymbolAddress((void**)&ctx, g_ctx);

    cudaFuncSetAttribute(scores_s3r,
                         cudaFuncAttributeMaxDynamicSharedMemorySize, 6 * TSB_);

    const int NH = BH_ * N_ * D_;         // 4194304

    fused_front<<<768, 256>>>(q, wq_w, wq_b, Qh,
                              k, wk_w, wk_b, Kh,
                              v, wv_w, wv_b, Vh);

    split3_qk<<<2 * NH / 256, 256>>>(NH);

    dim3 gSc(N_ / 128, N_ / 128, BH_);    // 16 x 16 x 32
    scores_s3r<<<gSc, 256, 6 * TSB_>>>();

    topk_pv_kernel<<<(B_ * N_ * H_) / 4, 128>>>();

    dim3 gO(HID_ / 128, M_ / 128);        // 8 x 32
    hmma_o<<<gO, 256>>>(ctx, wo_w, wo_b, out);
}

// round 13
// speedup vs baseline: 1.3697x; 1.0145x over previous
#include <cuda_runtime.h>
#include <cuda_bf16.h>
#include <cstdint>
#include <cstddef>
#include <math.h>

#define B_   2
#define N_   2048
#define HID_ 1024
#define H_   16
#define D_   64
#define BH_  (B_*H_)     // 32
#define M_   (B_*N_)     // 4096
#define TOPK_ 64

// scratch
__device__ float g_Vh[BH_*N_*D_];
__device__ unsigned g_S[134217728];           // 537 MB [bh][q][k]  FLIPPED fp32 bits
__device__ float g_ctx[M_*HID_];

// 3-term splits of (projected, scaled) Q / K  (h/m/l each), written directly
// by the projection epilogue
__device__ __nv_bfloat16 g_Q3[3][BH_*N_*D_];
__device__ __nv_bfloat16 g_K3[3][BH_*N_*D_];

// ---------------------------------------------------------------------------
#define LDSM_X4(r0,r1,r2,r3,addr) \
    asm volatile("ldmatrix.sync.aligned.m8n8.x4.shared.b16 {%0,%1,%2,%3}, [%4];" \
        : "=r"(r0), "=r"(r1), "=r"(r2), "=r"(r3) : "r"(addr))
#define LDSM_X2(r0,r1,addr) \
    asm volatile("ldmatrix.sync.aligned.m8n8.x2.shared.b16 {%0,%1}, [%2];" \
        : "=r"(r0), "=r"(r1) : "r"(addr))
#define MMA16816(c0,c1,c2,c3,a0,a1,a2,a3,b0,b1) \
    asm volatile("mma.sync.aligned.m16n8k16.row.col.f32.bf16.bf16.f32 " \
        "{%0,%1,%2,%3}, {%4,%5,%6,%7}, {%8,%9}, {%0,%1,%2,%3};" \
        : "+f"(c0), "+f"(c1), "+f"(c2), "+f"(c3) \
        : "r"(a0), "r"(a1), "r"(a2), "r"(a3), "r"(b0), "r"(b1))

__device__ __forceinline__ uint32_t smem_u32(const void* p) {
    uint32_t a;
    asm("{ .reg .u64 t; cvta.to.shared.u64 t, %1; cvt.u32.u64 %0, t; }"
        : "=r"(a) : "l"(p));
    return a;
}
__device__ __forceinline__ uint32_t bf2pack(__nv_bfloat16 a, __nv_bfloat16 b) {
    __nv_bfloat162 t; t.x = a; t.y = b;
    return *(uint32_t*)&t;
}
__device__ __forceinline__ unsigned fflip(float f) {
    unsigned u = __float_as_uint(f);
    return (u & 0x80000000u) ? ~u : (u | 0x80000000u);
}
__device__ __forceinline__ float funflip(unsigned u) {
    unsigned v = (u & 0x80000000u) ? (u & 0x7FFFFFFFu) : ~u;
    return __uint_as_float(v);
}

// ---------------------------------------------------------------------------
// fp32 SGEMM body. Mainloop BIT-IDENTICAL to R11. Epilogue computes the same
// (c+b)*oscale values, then applies the SAME 3-term split formula inline and
// writes bf16 h/m/l planes directly (identical bits to old split3_qk output).
// ---------------------------------------------------------------------------
#define ASF(cur,kk,c) Asp[((cur)*8+(kk))*128+(c)]
#define BSF(cur,kk,c) Bsp[((cur)*8+(kk))*128+(c)]

__device__ __forceinline__ void sgemm_split3_body(
    const float* __restrict__ X, const float* __restrict__ W,
    const float* __restrict__ bias,
    __nv_bfloat16* __restrict__ Oh, __nv_bfloat16* __restrict__ Om,
    __nv_bfloat16* __restrict__ Ol,
    float oscale, int n0, int o0, char* fbuf)
{
    const int K = HID_;
    float* Asp = (float*)fbuf;            // [2][8][128] = 8192 B
    float* Bsp = (float*)(fbuf + 8192);   // 8192 B
    int tid = threadIdx.x;

    int lrow = tid >> 1;
    int lkq  = (tid & 1) * 4;
    const float* Xp = X + (size_t)(n0 + lrow) * K + lkq;
    const float* Wp = W + (size_t)(o0 + lrow) * K + lkq;

    {
        float4 xa = *(const float4*)Xp;
        float4 wa = *(const float4*)Wp;
        ASF(0, lkq+0, lrow) = xa.x; ASF(0, lkq+1, lrow) = xa.y;
        ASF(0, lkq+2, lrow) = xa.z; ASF(0, lkq+3, lrow) = xa.w;
        BSF(0, lkq+0, lrow) = wa.x; BSF(0, lkq+1, lrow) = wa.y;
        BSF(0, lkq+2, lrow) = wa.z; BSF(0, lkq+3, lrow) = wa.w;
    }
    __syncthreads();

    int tx = tid & 15, ty = tid >> 4;
    float c[8][8];
#pragma unroll
    for (int i = 0; i < 8; i++)
#pragma unroll
        for (int j = 0; j < 8; j++) c[i][j] = 0.f;

    const int NSTEP = K / 8;
#pragma unroll 2
    for (int k0 = 0; k0 < NSTEP; k0++) {
        int cur = k0 & 1;
        float4 xn, wn;
        if (k0 < NSTEP - 1) {
            xn = *(const float4*)(Xp + (k0 + 1) * 8);
            wn = *(const float4*)(Wp + (k0 + 1) * 8);
        }
#pragma unroll
        for (int kk = 0; kk < 8; kk++) {
            float a[8], b[8];
            *(float4*)&a[0] = *(const float4*)&ASF(cur, kk, ty*8);
            *(float4*)&a[4] = *(const float4*)&ASF(cur, kk, ty*8+4);
            *(float4*)&b[0] = *(const float4*)&BSF(cur, kk, tx*8);
            *(float4*)&b[4] = *(const float4*)&BSF(cur, kk, tx*8+4);
#pragma unroll
            for (int i = 0; i < 8; i++)
#pragma unroll
                for (int j = 0; j < 8; j++)
                    c[i][j] += a[i] * b[j];
        }
        if (k0 < NSTEP - 1) {
            int nxt = cur ^ 1;
            ASF(nxt, lkq+0, lrow) = xn.x; ASF(nxt, lkq+1, lrow) = xn.y;
            ASF(nxt, lkq+2, lrow) = xn.z; ASF(nxt, lkq+3, lrow) = xn.w;
            BSF(nxt, lkq+0, lrow) = wn.x; BSF(nxt, lkq+1, lrow) = wn.y;
            BSF(nxt, lkq+2, lrow) = wn.z; BSF(nxt, lkq+3, lrow) = wn.w;
            __syncthreads();
        }
    }

    float bfr[8];
#pragma unroll
    for (int j = 0; j < 8; j++) bfr[j] = __ldg(bias + o0 + tx*8 + j);

#pragma unroll
    for (int i = 0; i < 8; i++) {
        int n = n0 + ty * 8 + i;
        int o = o0 + tx * 8;
        int b = n >> 11, nn = n & 2047;
        int h = o >> 6,  d  = o & 63;
        size_t idx = (((size_t)(b * H_ + h) * N_) + nn) * D_ + d;

        float val[8];
#pragma unroll
        for (int j = 0; j < 8; j++) val[j] = (c[i][j] + bfr[j]) * oscale;

        __nv_bfloat16 hh[8], mm[8], ll[8];
#pragma unroll
        for (int j = 0; j < 8; j++) {
            hh[j] = __float2bfloat16_rn(val[j]);
            float r1 = val[j] - __bfloat162float(hh[j]);
            mm[j] = __float2bfloat16_rn(r1);
            float r2 = r1 - __bfloat162float(mm[j]);
            ll[j] = __float2bfloat16_rn(r2);
        }
        uint4 hv, mv, lv;
        hv.x = bf2pack(hh[0], hh[1]); hv.y = bf2pack(hh[2], hh[3]);
        hv.z = bf2pack(hh[4], hh[5]); hv.w = bf2pack(hh[6], hh[7]);
        mv.x = bf2pack(mm[0], mm[1]); mv.y = bf2pack(mm[2], mm[3]);
        mv.z = bf2pack(mm[4], mm[5]); mv.w = bf2pack(mm[6], mm[7]);
        lv.x = bf2pack(ll[0], ll[1]); lv.y = bf2pack(ll[2], ll[3]);
        lv.z = bf2pack(ll[4], ll[5]); lv.w = bf2pack(ll[6], ll[7]);
        *(uint4*)(Oh + idx) = hv;
        *(uint4*)(Om + idx) = mv;
        *(uint4*)(Ol + idx) = lv;
    }
}

// ---------------------------------------------------------------------------
// HMMA split-bf16 GEMM body with ON-THE-FLY fp32 -> hi/lo split (verbatim R11)
// ---------------------------------------------------------------------------
#define TS_   5120          // tile size in bf16 entries (128 rows * 40)

__device__ __forceinline__ void hmma_f32_body(
    const float* __restrict__ Af, const float* __restrict__ Bf,
    const float* __restrict__ bias, float* __restrict__ Out,
    int mode, int n0, int o0, char* fbuf)
{
    __nv_bfloat16* smbuf = (__nv_bfloat16*)fbuf;   // 4 tiles, 40960 B
    int tid  = threadIdx.x;
    int wid  = tid >> 5, lane = tid & 31;
    int wm   = wid >> 2;
    int wn   = wid & 3;

    uint32_t smb = smem_u32(smbuf);

    float c[4][4][4];
#pragma unroll
    for (int mt = 0; mt < 4; mt++)
#pragma unroll
        for (int nt = 0; nt < 4; nt++)
#pragma unroll
            for (int r = 0; r < 4; r++) c[mt][nt][r] = 0.f;

    int rowm[4], segm[4];
    const float* gbase[4];
#pragma unroll
    for (int j = 0; j < 4; j++) {
        int isB  = j >> 1;
        int sub  = ((j & 1) << 8) + tid;       // 0..511
        rowm[j] = sub >> 2; segm[j] = sub & 3;
        const float* base = isB ? Bf : Af;
        int grow = (isB ? o0 : n0) + rowm[j];
        gbase[j] = base + (size_t)grow * HID_ + segm[j] * 8;
    }
    uint32_t soffh[4], soffl[4];
#pragma unroll
    for (int j = 0; j < 4; j++) {
        int isB = j >> 1;
        uint32_t e = (uint32_t)(rowm[j] * 40 + segm[j] * 8);
        soffh[j] = (uint32_t)(((isB ? 2 : 0) * TS_ + e) * 2);
        soffl[j] = (uint32_t)(((isB ? 3 : 1) * TS_ + e) * 2);
    }

    uint32_t laneA = (uint32_t)((lane & 15) * 80 + (lane >> 4) * 16);
    uint32_t laneB = (uint32_t)((lane & 7) * 80 + ((lane >> 3) & 1) * 16);
    uint32_t aBase0 = smb + (uint32_t)(wm * 64 * 80) + laneA;
    uint32_t bBase0 = smb + (uint32_t)(wn * 32 * 80) + laneB;

    float4 pf0[4], pf1[4];
#pragma unroll
    for (int j = 0; j < 4; j++) {
        pf0[j] = *(const float4*)gbase[j];
        pf1[j] = *(const float4*)(gbase[j] + 4);
    }
#pragma unroll
    for (int j = 0; j < 4; j++) {
        float fv[8] = {pf0[j].x, pf0[j].y, pf0[j].z, pf0[j].w,
                       pf1[j].x, pf1[j].y, pf1[j].z, pf1[j].w};
        __nv_bfloat16 hh[8], ll[8];
#pragma unroll
        for (int e = 0; e < 8; e++) {
            hh[e] = __float2bfloat16_rn(fv[e]);
            ll[e] = __float2bfloat16_rn(fv[e] - __bfloat162float(hh[e]));
        }
        uint4 hv, lv;
        hv.x = bf2pack(hh[0], hh[1]); hv.y = bf2pack(hh[2], hh[3]);
        hv.z = bf2pack(hh[4], hh[5]); hv.w = bf2pack(hh[6], hh[7]);
        lv.x = bf2pack(ll[0], ll[1]); lv.y = bf2pack(ll[2], ll[3]);
        lv.z = bf2pack(ll[4], ll[5]); lv.w = bf2pack(ll[6], ll[7]);
        *(uint4*)((char*)smbuf + soffh[j]) = hv;
        *(uint4*)((char*)smbuf + soffl[j]) = lv;
    }
    __syncthreads();

    for (int kc = 0; kc < 32; kc++) {
        if (kc < 31) {
#pragma unroll
            for (int j = 0; j < 4; j++) {
                pf0[j] = *(const float4*)(gbase[j] + (kc + 1) * 32);
                pf1[j] = *(const float4*)(gbase[j] + (kc + 1) * 32 + 4);
            }
        }

#pragma unroll
        for (int pass = 0; pass < 3; pass++) {
            uint32_t aT = aBase0 + (uint32_t)(((pass == 2) ? TS_ : 0) * 2);
            uint32_t bT = bBase0 + (uint32_t)((((pass == 1) ? 3 : 2) * TS_) * 2);
#pragma unroll
            for (int k16 = 0; k16 < 2; k16++) {
                uint32_t a[4][4];
#pragma unroll
                for (int mt = 0; mt < 4; mt++)
                    LDSM_X4(a[mt][0], a[mt][1], a[mt][2], a[mt][3],
                            aT + (uint32_t)(mt * 1280 + k16 * 32));
                uint32_t bf[4][2];
#pragma unroll
                for (int nt = 0; nt < 4; nt++)
                    LDSM_X2(bf[nt][0], bf[nt][1],
                            bT + (uint32_t)(nt * 640 + k16 * 32));
#pragma unroll
                for (int mt = 0; mt < 4; mt++)
#pragma unroll
                    for (int nt = 0; nt < 4; nt++)
                        MMA16816(c[mt][nt][0], c[mt][nt][1], c[mt][nt][2], c[mt][nt][3],
                                 a[mt][0], a[mt][1], a[mt][2], a[mt][3],
                                 bf[nt][0], bf[nt][1]);
            }
        }

        if (kc < 31) {
            __syncthreads();
#pragma unroll
            for (int j = 0; j < 4; j++) {
                float fv[8] = {pf0[j].x, pf0[j].y, pf0[j].z, pf0[j].w,
                               pf1[j].x, pf1[j].y, pf1[j].z, pf1[j].w};
                __nv_bfloat16 hh[8], ll[8];
#pragma unroll
                for (int e = 0; e < 8; e++) {
                    hh[e] = __float2bfloat16_rn(fv[e]);
                    ll[e] = __float2bfloat16_rn(fv[e] - __bfloat162float(hh[e]));
                }
                uint4 hv, lv;
                hv.x = bf2pack(hh[0], hh[1]); hv.y = bf2pack(hh[2], hh[3]);
                hv.z = bf2pack(hh[4], hh[5]); hv.w = bf2pack(hh[6], hh[7]);
                lv.x = bf2pack(ll[0], ll[1]); lv.y = bf2pack(ll[2], ll[3]);
                lv.z = bf2pack(ll[4], ll[5]); lv.w = bf2pack(ll[6], ll[7]);
                *(uint4*)((char*)smbuf + soffh[j]) = hv;
                *(uint4*)((char*)smbuf + soffl[j]) = lv;
            }
            __syncthreads();
        }
    }

    int row_l = lane >> 2;
    int col_l = (lane & 3) * 2;
#pragma unroll
    for (int nt = 0; nt < 4; nt++) {
        int o = o0 + wn * 32 + nt * 8 + col_l;
        float bv0 = __ldg(bias + o);
        float bv1 = __ldg(bias + o + 1);
#pragma unroll
        for (int mt = 0; mt < 4; mt++) {
            int n = n0 + wm * 64 + mt * 16 + row_l;
#pragma unroll
            for (int half = 0; half < 2; half++) {
                int nn2 = n + half * 8;
                size_t idx;
                if (mode == 0) {
                    int b = nn2 >> 11, nr = nn2 & 2047;
                    int h = o >> 6,  d0 = o & 63;
                    idx = (((size_t)(b * H_ + h) * N_) + nr) * D_ + d0;
                } else {
                    idx = (size_t)nn2 * HID_ + o;
                }
                float2 vv;
                vv.x = c[mt][nt][half * 2 + 0] + bv0;
                vv.y = c[mt][nt][half * 2 + 1] + bv1;
                *(float2*)(Out + idx) = vv;
            }
        }
    }
}

// ---------------------------------------------------------------------------
// fused_front: Q/K fp32 proj (writing split3 planes directly) + V HMMA proj
// ---------------------------------------------------------------------------
__global__ __launch_bounds__(256, 2) void fused_front(
    const float* __restrict__ q,  const float* __restrict__ wq_w,
    const float* __restrict__ wq_b,
    const float* __restrict__ k,  const float* __restrict__ wk_w,
    const float* __restrict__ wk_b,
    const float* __restrict__ v,  const float* __restrict__ wv_w,
    const float* __restrict__ wv_b, float* __restrict__ Vh)
{
    __shared__ __align__(16) char fbuf[40960];
    int id = blockIdx.x;
    int r  = id % 3;
    int g  = id / 3;

    if (r < 2) {
        int t   = g * 2 + r;          // 0..511
        int z   = t >> 8;             // 0 = Q, 1 = K
        int rem = t & 255;
        int o0  = (rem & 7) * 128;
        int n0  = (rem >> 3) * 128;
        if (z == 0)
            sgemm_split3_body(q, wq_w, wq_b,
                              g_Q3[0], g_Q3[1], g_Q3[2],
                              0.125f, n0, o0, fbuf);
        else
            sgemm_split3_body(k, wk_w, wk_b,
                              g_K3[0], g_K3[1], g_K3[2],
                              1.0f, n0, o0, fbuf);
    } else {
        int t  = g;                   // 0..255
        int o0 = (t & 7) * 128;
        int n0 = (t >> 3) * 128;
        hmma_f32_body(v, wv_w, wv_b, Vh, 0, n0, o0, fbuf);
    }
}

// O projection standalone (after topk)
__global__ __launch_bounds__(256, 2) void hmma_o(
    const float* __restrict__ ctx, const float* __restrict__ wo_w,
    const float* __restrict__ wo_b, float* __restrict__ Out)
{
    __shared__ __align__(16) char fbuf[40960];
    hmma_f32_body(ctx, wo_w, wo_b, Out, 1,
                  blockIdx.y * 128, blockIdx.x * 128, fbuf);
}

// ---------------------------------------------------------------------------
// Scores (resident tiles, verbatim R11) -- epilogue stores FLIPPED bits.
// ---------------------------------------------------------------------------
#define STRB_ 144                 // row stride bytes
#define TSB_  (128 * STRB_)       // tile bytes = 18432

__global__ __launch_bounds__(256, 2) void scores_s3r(void)
{
    extern __shared__ __align__(16) char dsm[];
    int tid  = threadIdx.x;
    int wid  = tid >> 5, lane = tid & 31;
    int wm   = wid >> 2;
    int wn   = wid & 3;
    int bh   = blockIdx.z;
    int k0   = blockIdx.x * 128;
    int q0   = blockIdx.y * 128;

    uint32_t smb = smem_u32(dsm);

    const __nv_bfloat16* tsrc[6] = {
        g_Q3[0] + (size_t)bh * N_ * D_, g_Q3[1] + (size_t)bh * N_ * D_,
        g_Q3[2] + (size_t)bh * N_ * D_, g_K3[0] + (size_t)bh * N_ * D_,
        g_K3[1] + (size_t)bh * N_ * D_, g_K3[2] + (size_t)bh * N_ * D_ };

#pragma unroll
    for (int t = 0; t < 6; t++) {
        int r0 = (t < 3) ? q0 : k0;
#pragma unroll
        for (int it = 0; it < 4; it++) {
            int sub = it * 256 + tid;
            int row = sub >> 3, seg = sub & 7;
            *(uint4*)(dsm + t * TSB_ + row * STRB_ + seg * 16) =
                *(const uint4*)(tsrc[t] + (size_t)(r0 + row) * D_ + seg * 8);
        }
    }
    __syncthreads();

    float c[4][4][4];
#pragma unroll
    for (int mt = 0; mt < 4; mt++)
#pragma unroll
        for (int nt = 0; nt < 4; nt++)
#pragma unroll
            for (int r = 0; r < 4; r++) c[mt][nt][r] = 0.f;

    uint32_t laneA = (uint32_t)((lane & 15) * STRB_ + (lane >> 4) * 16);
    uint32_t laneB = (uint32_t)((lane & 7) * STRB_ + ((lane >> 3) & 1) * 16);
    uint32_t aBase0 = smb + (uint32_t)(wm * 64 * STRB_) + laneA;
    uint32_t bBase0 = smb + (uint32_t)(wn * 32 * STRB_) + laneB;

#pragma unroll
    for (int rnd = 0; rnd < 2; rnd++) {
#pragma unroll
        for (int kc = 0; kc < 2; kc++) {
            int npass = rnd ? 2 : 4;
            for (int p = 0; p < npass; p++) {
                int at, bt;
                if (rnd == 0) { at = p >> 1;           bt = 3 + (p & 1); }
                else          { at = (p == 0) ? 0 : 2; bt = (p == 0) ? 5 : 3; }
                uint32_t aT = aBase0 + (uint32_t)(at * TSB_);
                uint32_t bT = bBase0 + (uint32_t)(bt * TSB_);
#pragma unroll
                for (int k16 = 0; k16 < 2; k16++) {
                    uint32_t coloff = (uint32_t)(kc * 64 + k16 * 32);
                    uint32_t a[4][4];
#pragma unroll
                    for (int mt = 0; mt < 4; mt++)
                        LDSM_X4(a[mt][0], a[mt][1], a[mt][2], a[mt][3],
                                aT + (uint32_t)(mt * 16 * STRB_) + coloff);
                    uint32_t bf[4][2];
#pragma unroll
                    for (int nt = 0; nt < 4; nt++)
                        LDSM_X2(bf[nt][0], bf[nt][1],
                                bT + (uint32_t)(nt * 8 * STRB_) + coloff);
#pragma unroll
                    for (int mt = 0; mt < 4; mt++)
#pragma unroll
                        for (int nt = 0; nt < 4; nt++)
                            MMA16816(c[mt][nt][0], c[mt][nt][1], c[mt][nt][2], c[mt][nt][3],
                                     a[mt][0], a[mt][1], a[mt][2], a[mt][3],
                                     bf[nt][0], bf[nt][1]);
                }
            }
        }
    }

    int row_l = lane >> 2;
    int col_l = (lane & 3) * 2;
    unsigned* Sb = g_S + (size_t)bh * N_ * N_;
#pragma unroll
    for (int nt = 0; nt < 4; nt++) {
        int o = k0 + wn * 32 + nt * 8 + col_l;
#pragma unroll
        for (int mt = 0; mt < 4; mt++) {
            int n = q0 + wm * 64 + mt * 16 + row_l;
#pragma unroll
            for (int half = 0; half < 2; half++) {
                int qq = n + half * 8;
                uint2 vv;
                vv.x = fflip(c[mt][nt][half * 2 + 0]);
                vv.y = fflip(c[mt][nt][half * 2 + 1]);
                *(uint2*)(Sb + (size_t)qq * N_ + o) = vv;
            }
        }
    }
}

// ---------------------------------------------------------------------------
// topk_v4 (logic verbatim R11), 8 warps/block for occupancy.
// ---------------------------------------------------------------------------
#define CAP_ 320

__global__ __launch_bounds__(256) void topk_pv_kernel(void)
{
    __shared__ unsigned       candV[8][CAP_];
    __shared__ unsigned short candI[8][CAP_];
    __shared__ int   sk[8][64];
    __shared__ float sv[8][64];
    __shared__ float pw[8][64];
    __shared__ int   ek[8][64];

    int w    = threadIdx.x >> 5;
    int lane = threadIdx.x & 31;
    int gq   = blockIdx.x * 8 + w;
    int bh   = gq >> 11;
    int qr   = gq & 2047;
    unsigned ltmask = (1u << lane) - 1u;

    const unsigned* Sb = g_S + ((size_t)bh * N_ + qr) * N_;

    // load 2048 flipped scores into 64 regs; track per-lane top-2
    unsigned u[64];
    unsigned m1 = 0u, m2 = 0u;
#pragma unroll
    for (int it = 0; it < 16; it++) {
        uint4 f = ((const uint4*)Sb)[it * 32 + lane];
        u[it*4+0] = f.x; u[it*4+1] = f.y; u[it*4+2] = f.z; u[it*4+3] = f.w;
#pragma unroll
        for (int r = 0; r < 4; r++) {
            unsigned x = u[it*4+r];
            if (x > m1) { m2 = m1; m1 = x; }
            else if (x > m2) { m2 = x; }
        }
    }
    unsigned T0 = __reduce_min_sync(0xffffffffu, m2);   // >=64 values >= T0

    // per-lane candidate count + exclusive scan
    int cnt = 0;
#pragma unroll
    for (int i = 0; i < 64; i++) cnt += (u[i] >= T0);
    int off = cnt;
#pragma unroll
    for (int d = 1; d < 32; d <<= 1) {
        int t = __shfl_up_sync(0xffffffffu, off, d);
        if (lane >= d) off += t;
    }
    int nc = __shfl_sync(0xffffffffu, off, 31);
    off -= cnt;

    // compact candidates (lane-major order)
    if (nc <= CAP_) {
        int o2 = off;
#pragma unroll
        for (int i = 0; i < 64; i++) {
            if (u[i] >= T0) {
                candV[w][o2] = u[i];
                candI[w][o2] = (unsigned short)((i >> 2) * 128 + lane * 4 + (i & 3));
                o2++;
            }
        }
    }
    __syncwarp();

    unsigned X = 0u;
    if (nc <= CAP_) {
        unsigned cu[CAP_/32];
        unsigned short ci[CAP_/32];
#pragma unroll
        for (int jj = 0; jj < CAP_/32; jj++) {
            int idx = lane + jj * 32;
            cu[jj] = (idx < nc) ? candV[w][idx] : 0u;
            ci[jj] = (idx < nc) ? candI[w][idx] : 0;
        }
        unsigned t = 0u;
        for (int bit = 31; bit >= 0; bit--) {
            unsigned tt = t | (1u << bit);
            int c = 0;
#pragma unroll
            for (int jj = 0; jj < CAP_/32; jj++) c += (cu[jj] >= tt);
            c = __reduce_add_sync(0xffffffffu, c);
            if (c >= TOPK_) {
                t = tt;
                if (c == TOPK_) break;
            }
        }
        X = t;

        int g1 = 0, g2 = 0;
#pragma unroll
        for (int jj = 0; jj < CAP_/32; jj++) {
            int idx = lane + jj * 32;
            bool valid = (idx < nc);
            unsigned x = cu[jj];
            bool gt = valid && (x > X), eq = valid && (x == X);
            unsigned mg = __ballot_sync(0xffffffffu, gt);
            unsigned me = __ballot_sync(0xffffffffu, eq);
            if (gt) {
                int p = g1 + __popc(mg & ltmask);
                sk[w][p] = ci[jj];
                sv[w][p] = funflip(x);
            }
            if (eq) {
                int p = g2 + __popc(me & ltmask);
                if (p < 64) ek[w][p] = ci[jj];
            }
            g1 += __popc(mg);
            g2 += __popc(me);
        }
        __syncwarp();
        if (lane == 0) {
            int need = TOPK_ - g1;
            int ec   = g2 > 64 ? 64 : g2;
            float xv = funflip(X);
            for (int s2 = 0; s2 < need; s2++) {
                int best = 0x7FFFFFFF, bi = 0;
                for (int e = 0; e < ec; e++) {
                    int v2 = ek[w][e];
                    if (v2 < best) { best = v2; bi = e; }
                }
                ek[w][bi] = 0x7FFFFFFF;
                sk[w][g1 + s2] = best;
                sv[w][g1 + s2] = xv;
            }
        }
    } else {
        // slow fallback from regs (prob ~0)
        unsigned t = 0u;
        for (int bit = 31; bit >= 0; bit--) {
            unsigned tt = t | (1u << bit);
            int c = 0;
#pragma unroll
            for (int i = 0; i < 64; i++) c += (u[i] >= tt);
            c = __reduce_add_sync(0xffffffffu, c);
            if (c >= TOPK_) {
                t = tt;
                if (c == TOPK_) break;
            }
        }
        X = t;
        int g1 = 0, g2 = 0;
        for (int i = 0; i < 64; i++) {
            unsigned x = u[i];
            int kix = (i >> 2) * 128 + lane * 4 + (i & 3);
            bool gt = (x > X), eq = (x == X);
            unsigned mg = __ballot_sync(0xffffffffu, gt);
            unsigned me = __ballot_sync(0xffffffffu, eq);
            if (gt) {
                int p = g1 + __popc(mg & ltmask);
                sk[w][p] = kix;
                sv[w][p] = funflip(x);
            }
            if (eq) {
                int p = g2 + __popc(me & ltmask);
                if (p < 64) ek[w][p] = kix;
            }
            g1 += __popc(mg);
            g2 += __popc(me);
        }
        __syncwarp();
        if (lane == 0) {
            int need = TOPK_ - g1;
            int ec   = g2 > 64 ? 64 : g2;
            float xv = funflip(X);
            for (int s2 = 0; s2 < need; s2++) {
                int best = 0x7FFFFFFF, bi = 0;
                for (int e = 0; e < ec; e++) {
                    int v2 = ek[w][e];
                    if (v2 < best) { best = v2; bi = e; }
                }
                ek[w][bi] = 0x7FFFFFFF;
                sk[w][g1 + s2] = best;
                sv[w][g1 + s2] = xv;
            }
        }
    }
    __syncwarp();

    // softmax over selected 64
    float v0 = sv[w][lane];
    float v1 = sv[w][lane + 32];
    float mx = funflip(__reduce_max_sync(0xffffffffu,
                 (unsigned)max(fflip(v0), fflip(v1))));
    float p0 = expf(v0 - mx);
    float p1 = expf(v1 - mx);
    pw[w][lane]      = p0;
    pw[w][lane + 32] = p1;
    float z = p0 + p1;
#pragma unroll
    for (int offx = 16; offx > 0; offx >>= 1)
        z += __shfl_xor_sync(0xffffffffu, z, offx);
    float invZ = 1.0f / z;

    // PV
    const float* Vb = g_Vh + (size_t)bh * N_ * D_;
    float acc0 = 0.f, acc1 = 0.f;
#pragma unroll 8
    for (int j = 0; j < 64; j++) {
        float p  = pw[w][j];
        int   kj = sk[w][j];
        acc0 += p * __ldg(Vb + (size_t)kj * D_ + lane);
        acc1 += p * __ldg(Vb + (size_t)kj * D_ + lane + 32);
    }

    int b = bh >> 4, h = bh & 15;
    size_t obase = ((size_t)(b * N_ + qr)) * HID_ + h * D_ + lane;
    g_ctx[obase]      = acc0 * invZ;
    g_ctx[obase + 32] = acc1 * invZ;
}

// ---------------------------------------------------------------------------
extern "C" void kernel_launch(void* const* d_in, const int* in_sizes, int n_in,
                              void* d_out, int out_size)
{
    const float* q    = (const float*)d_in[0];
    const float* k    = (const float*)d_in[1];
    const float* v    = (const float*)d_in[2];
    const float* wq_w = (const float*)d_in[5];
    const float* wq_b = (const float*)d_in[6];
    const float* wk_w = (const float*)d_in[7];
    const float* wk_b = (const float*)d_in[8];
    const float* wv_w = (const float*)d_in[9];
    const float* wv_b = (const float*)d_in[10];
    const float* wo_w = (const float*)d_in[11];
    const float* wo_b = (const float*)d_in[12];
    float* out = (float*)d_out;

    float *Vh, *ctx;
    cudaGetSymbolAddress((void**)&Vh,  g_Vh);
    cudaGetSymbolAddress((void**)&ctx, g_ctx);

    cudaFuncSetAttribute(scores_s3r,
                         cudaFuncAttributeMaxDynamicSharedMemorySize, 6 * TSB_);

    // Q/K fp32 projections (epilogue emits bf16 split3 planes) + V HMMA proj
    fused_front<<<768, 256>>>(q, wq_w, wq_b,
                              k, wk_w, wk_b,
                              v, wv_w, wv_b, Vh);

    // scores: 6-pass split-3 bf16 HMMA, resident tiles, flipped-bit output
    dim3 gSc(N_ / 128, N_ / 128, BH_);    // 16 x 16 x 32
    scores_s3r<<<gSc, 256, 6 * TSB_>>>();

    // exact top-64 + softmax + PV (8 warps/block)
    topk_pv_kernel<<<(B_ * N_ * H_) / 8, 256>>>();

    // O projection (on-the-fly split HMMA)
    dim3 gO(HID_ / 128, M_ / 128);        // 8 x 32
    hmma_o<<<gO, 256>>>(ctx, wo_w, wo_b, out);
}